// round 12
// baseline (speedup 1.0000x reference)
#include <cuda_runtime.h>
#include <cuda_fp16.h>
#include <math.h>
#include <stdint.h>

// Problem constants
#define S 2048
#define D_MODEL 2560
#define NUM_HEADS 32
#define NUM_KV_HEADS 8
#define HEAD_DIM 128
#define QDIM (NUM_HEADS * HEAD_DIM)     // 4096
#define KVDIM (NUM_KV_HEADS * HEAD_DIM) // 1024
#define QKVDIM (QDIM + 2 * KVDIM)       // 6144
#define EPS 1e-6f
#define ROPE_THETA 5000000.0f

// Scratch (no allocs allowed -> __device__ globals)
__device__ __half g_Xh[S * D_MODEL];
__device__ __half g_Wqkvh[QKVDIM * D_MODEL];
__device__ __half g_Woh[D_MODEL * QDIM];
__device__ float  g_QKV[S * QKVDIM];
__device__ __half g_Qh[S * QDIM];
__device__ __half g_Krh[NUM_KV_HEADS * S * HEAD_DIM];
__device__ __half g_Vrh[NUM_KV_HEADS * S * HEAD_DIM];
__device__ __half g_Oh[S * QDIM];

// ----------------------------------------------------------------------------
// helpers
// ----------------------------------------------------------------------------
__device__ __forceinline__ void mma_f16(float* d, const unsigned* a, const unsigned* b) {
    asm volatile(
        "mma.sync.aligned.m16n8k16.row.col.f32.f16.f16.f32 "
        "{%0,%1,%2,%3}, {%4,%5,%6,%7}, {%8,%9}, {%0,%1,%2,%3};"
        : "+f"(d[0]), "+f"(d[1]), "+f"(d[2]), "+f"(d[3])
        : "r"(a[0]), "r"(a[1]), "r"(a[2]), "r"(a[3]), "r"(b[0]), "r"(b[1]));
}

__device__ __forceinline__ void ldsm_x4(unsigned* r, uint32_t addr) {
    asm volatile("ldmatrix.sync.aligned.m8n8.x4.shared.b16 {%0,%1,%2,%3}, [%4];"
                 : "=r"(r[0]), "=r"(r[1]), "=r"(r[2]), "=r"(r[3]) : "r"(addr));
}

__device__ __forceinline__ void cp_async16(void* smem_dst, const void* gmem_src) {
    unsigned saddr = (unsigned)__cvta_generic_to_shared(smem_dst);
    asm volatile("cp.async.cg.shared.global [%0], [%1], 16;" :: "r"(saddr), "l"(gmem_src));
}
#define CP_COMMIT() asm volatile("cp.async.commit_group;")

__device__ __forceinline__ uint32_t smem_u32(const void* p) {
    uint32_t a;
    asm("{ .reg .u64 t; cvta.to.shared.u64 t, %1; cvt.u32.u64 %0, t; }" : "=r"(a) : "l"(p));
    return a;
}

// ----------------------------------------------------------------------------
// Fused conversion of all inputs to fp16 (RNE). One launch.
// ----------------------------------------------------------------------------
#define R_N1 (S * D_MODEL / 4)
#define R_N2 (QDIM * D_MODEL / 4)
#define R_N3 (KVDIM * D_MODEL / 4)
#define R_TOT (R_N1 + R_N2 + 2 * R_N3 + R_N2)

__global__ void round_all_kernel(const float* __restrict__ x,
                                 const float* __restrict__ Wq,
                                 const float* __restrict__ Wk,
                                 const float* __restrict__ Wv,
                                 const float* __restrict__ Wo) {
    long i = (long)blockIdx.x * blockDim.x + threadIdx.x;
    if (i >= R_TOT) return;
    const float4* src;
    __half* dst;
    if (i < R_N1) {
        src = (const float4*)x;
        dst = g_Xh;
    } else if (i < R_N1 + R_N2) {
        i -= R_N1;
        src = (const float4*)Wq;
        dst = g_Wqkvh;
    } else if (i < R_N1 + R_N2 + R_N3) {
        i -= R_N1 + R_N2;
        src = (const float4*)Wk;
        dst = g_Wqkvh + (size_t)QDIM * D_MODEL;
    } else if (i < R_N1 + R_N2 + 2 * R_N3) {
        i -= R_N1 + R_N2 + R_N3;
        src = (const float4*)Wv;
        dst = g_Wqkvh + (size_t)(QDIM + KVDIM) * D_MODEL;
    } else {
        i -= R_N1 + R_N2 + 2 * R_N3;
        src = (const float4*)Wo;
        dst = g_Woh;
    }
    float4 v = src[i];
    __half2 h0 = __floats2half2_rn(v.x, v.y);
    __half2 h1 = __floats2half2_rn(v.z, v.w);
    uint2 pk = make_uint2(*(unsigned*)&h0, *(unsigned*)&h1);
    *(uint2*)&dst[i * 4] = pk;
}

// ----------------------------------------------------------------------------
// fp16 NT GEMM 128x64 (QKV projection). Unchanged from round 11.
// ----------------------------------------------------------------------------
#define BM4 128
#define BN4 64
#define BK4 64
#define ROWB 144
#define STG4_B ((BM4 + BN4) * ROWB)       // 27648
#define G4_SMEM (2 * STG4_B)              // 55296

__global__ __launch_bounds__(128) void gemm_f16(const __half* __restrict__ A,
                                                const __half* __restrict__ B,
                                                float* __restrict__ C,
                                                int M, int N, int K, int ldc) {
    extern __shared__ char sm4[];
    const uint32_t sbase = smem_u32(sm4);

    const int tid = threadIdx.x;
    const int warp = tid >> 5;
    const int lane = tid & 31;
    const int r = lane >> 2;
    const int cc = lane & 3;
    const int bm0 = blockIdx.y * BM4;
    const int bn0 = blockIdx.x * BN4;
    const int nk = K / BK4;

    const uint32_t lmrow = (lane & 15);
    const uint32_t lmk = (lane >> 4) * 16;

    auto issue = [&](int kt) {
        char* As = sm4 + (kt & 1) * STG4_B;
        char* Bs = As + BM4 * ROWB;
        const int k0 = kt * BK4;
#pragma unroll
        for (int i = 0; i < 8; i++) {
            int task = tid + i * 128;
            int row = task >> 3, ch = task & 7;
            cp_async16(As + row * ROWB + ch * 16,
                       &A[(size_t)(bm0 + row) * K + k0 + ch * 8]);
        }
#pragma unroll
        for (int i = 0; i < 4; i++) {
            int task = tid + i * 128;
            int row = task >> 3, ch = task & 7;
            cp_async16(Bs + row * ROWB + ch * 16,
                       &B[(size_t)(bn0 + row) * K + k0 + ch * 8]);
        }
        CP_COMMIT();
    };

    issue(0);
    if (nk > 1) issue(1);

    float acc[2][8][4];
#pragma unroll
    for (int mt = 0; mt < 2; mt++)
#pragma unroll
        for (int nt = 0; nt < 8; nt++)
#pragma unroll
            for (int i = 0; i < 4; i++) acc[mt][nt][i] = 0.0f;

    for (int kt = 0; kt < nk; kt++) {
        if (kt == nk - 1) asm volatile("cp.async.wait_group 0;" ::: "memory");
        else              asm volatile("cp.async.wait_group 1;" ::: "memory");
        __syncthreads();

        const uint32_t stA = sbase + (kt & 1) * STG4_B;
        const uint32_t stB = stA + BM4 * ROWB;
        const uint32_t aAddr0 = stA + (warp * 32 + lmrow) * ROWB + lmk;
        const uint32_t bAddr0 = stB + lmrow * ROWB + lmk;

#pragma unroll
        for (int ks = 0; ks < 4; ks++) {
            const uint32_t ko = ks * 32;
            unsigned af[2][4];
            ldsm_x4(af[0], aAddr0 + ko);
            ldsm_x4(af[1], aAddr0 + 16 * ROWB + ko);
            unsigned bf[4][4];
#pragma unroll
            for (int p = 0; p < 4; p++)
                ldsm_x4(bf[p], bAddr0 + p * 16 * ROWB + ko);
#pragma unroll
            for (int mt = 0; mt < 2; mt++)
#pragma unroll
                for (int nt = 0; nt < 8; nt++) {
                    unsigned b[2] = { bf[nt >> 1][nt & 1], bf[nt >> 1][2 + (nt & 1)] };
                    mma_f16(acc[mt][nt], af[mt], b);
                }
        }
        __syncthreads();
        if (kt + 2 < nk) issue(kt + 2);
    }

#pragma unroll
    for (int mt = 0; mt < 2; mt++) {
#pragma unroll
        for (int nt = 0; nt < 8; nt++) {
            int row = bm0 + warp * 32 + mt * 16 + r;
            int col = bn0 + nt * 8 + 2 * cc;
            float2 v0 = make_float2(acc[mt][nt][0], acc[mt][nt][1]);
            float2 v1 = make_float2(acc[mt][nt][2], acc[mt][nt][3]);
            *(float2*)&C[(size_t)row * ldc + col] = v0;
            *(float2*)&C[(size_t)(row + 8) * ldc + col] = v1;
        }
    }
}

// ----------------------------------------------------------------------------
// fp16 NT GEMM 64x64 (output projection): finer tiles to kill wave
// quantization (1280 blocks @ 6 CTA/SM vs 640 @ 4). Same k-order -> identical
// numerics. 128 threads, 4 warps (2x2), warp tile 32x32.
// ----------------------------------------------------------------------------
#define BM5 64
#define BN5 64
#define STG5_B ((BM5 + BN5) * ROWB)       // 18432
#define G5_SMEM (2 * STG5_B)              // 36864

__global__ __launch_bounds__(128) void gemm_f16_64(const __half* __restrict__ A,
                                                   const __half* __restrict__ B,
                                                   float* __restrict__ C,
                                                   int M, int N, int K, int ldc) {
    extern __shared__ char sm5[];
    const uint32_t sbase = smem_u32(sm5);

    const int tid = threadIdx.x;
    const int warp = tid >> 5;
    const int lane = tid & 31;
    const int wm = warp >> 1;
    const int wn = warp & 1;
    const int r = lane >> 2;
    const int cc = lane & 3;
    const int bm0 = blockIdx.y * BM5;
    const int bn0 = blockIdx.x * BN5;
    const int nk = K / BK4;

    const uint32_t lmrow = (lane & 15);
    const uint32_t lmk = (lane >> 4) * 16;

    auto issue = [&](int kt) {
        char* As = sm5 + (kt & 1) * STG5_B;
        char* Bs = As + BM5 * ROWB;
        const int k0 = kt * BK4;
#pragma unroll
        for (int i = 0; i < 4; i++) {
            int task = tid + i * 128;
            int row = task >> 3, ch = task & 7;
            cp_async16(As + row * ROWB + ch * 16,
                       &A[(size_t)(bm0 + row) * K + k0 + ch * 8]);
        }
#pragma unroll
        for (int i = 0; i < 4; i++) {
            int task = tid + i * 128;
            int row = task >> 3, ch = task & 7;
            cp_async16(Bs + row * ROWB + ch * 16,
                       &B[(size_t)(bn0 + row) * K + k0 + ch * 8]);
        }
        CP_COMMIT();
    };

    issue(0);
    if (nk > 1) issue(1);

    float acc[2][4][4];
#pragma unroll
    for (int mt = 0; mt < 2; mt++)
#pragma unroll
        for (int nt = 0; nt < 4; nt++)
#pragma unroll
            for (int i = 0; i < 4; i++) acc[mt][nt][i] = 0.0f;

    for (int kt = 0; kt < nk; kt++) {
        if (kt == nk - 1) asm volatile("cp.async.wait_group 0;" ::: "memory");
        else              asm volatile("cp.async.wait_group 1;" ::: "memory");
        __syncthreads();

        const uint32_t stA = sbase + (kt & 1) * STG5_B;
        const uint32_t stB = stA + BM5 * ROWB;
        const uint32_t aAddr0 = stA + (wm * 32 + lmrow) * ROWB + lmk;
        const uint32_t bAddr0 = stB + (wn * 32 + lmrow) * ROWB + lmk;

#pragma unroll
        for (int ks = 0; ks < 4; ks++) {
            const uint32_t ko = ks * 32;
            unsigned af[2][4];
            ldsm_x4(af[0], aAddr0 + ko);
            ldsm_x4(af[1], aAddr0 + 16 * ROWB + ko);
            unsigned bf[2][4];
            ldsm_x4(bf[0], bAddr0 + ko);
            ldsm_x4(bf[1], bAddr0 + 16 * ROWB + ko);
#pragma unroll
            for (int mt = 0; mt < 2; mt++)
#pragma unroll
                for (int nt = 0; nt < 4; nt++) {
                    unsigned b[2] = { bf[nt >> 1][nt & 1], bf[nt >> 1][2 + (nt & 1)] };
                    mma_f16(acc[mt][nt], af[mt], b);
                }
        }
        __syncthreads();
        if (kt + 2 < nk) issue(kt + 2);
    }

#pragma unroll
    for (int mt = 0; mt < 2; mt++) {
#pragma unroll
        for (int nt = 0; nt < 4; nt++) {
            int row = bm0 + wm * 32 + mt * 16 + r;
            int col = bn0 + wn * 32 + nt * 8 + 2 * cc;
            float2 v0 = make_float2(acc[mt][nt][0], acc[mt][nt][1]);
            float2 v1 = make_float2(acc[mt][nt][2], acc[mt][nt][3]);
            *(float2*)&C[(size_t)row * ldc + col] = v0;
            *(float2*)&C[(size_t)(row + 8) * ldc + col] = v1;
        }
    }
}

// ----------------------------------------------------------------------------
// RMSNorm + RoPE for Q (writes g_Qh fp16)
// ----------------------------------------------------------------------------
__global__ void norm_rope_q_kernel(const float* __restrict__ src, __half* __restrict__ dst,
                                   const float* __restrict__ w) {
    int s = blockIdx.x;
    int h = blockIdx.y;
    int d = threadIdx.x;

    __shared__ float sh[HEAD_DIM];
    __shared__ float red[4];

    float x = src[(size_t)s * QKVDIM + h * HEAD_DIM + d];

    float sq = x * x;
#pragma unroll
    for (int off = 16; off > 0; off >>= 1)
        sq += __shfl_down_sync(0xffffffff, sq, off);
    if ((d & 31) == 0) red[d >> 5] = sq;
    __syncthreads();
    float var = (red[0] + red[1] + red[2] + red[3]) * (1.0f / HEAD_DIM);
    float r = rsqrtf(var + EPS);
    float xn = x * r * w[d];
    sh[d] = xn;
    __syncthreads();

    int f = d & 63;
    float inv_freq = powf(ROPE_THETA, -((float)f) / 64.0f);
    float ang = (float)s * inv_freq;
    float c = cosf(ang), sn = sinf(ang);
    float out;
    if (d < 64) out = xn * c - sh[d + 64] * sn;
    else        out = xn * c + sh[d - 64] * sn;

    dst[(size_t)s * QDIM + h * HEAD_DIM + d] = __float2half_rn(out);
}

// ----------------------------------------------------------------------------
// RMSNorm + RoPE for K (-> cache_k fp32 + g_Krh fp16) AND V copy
// ----------------------------------------------------------------------------
__global__ void norm_rope_kv_kernel(const float* __restrict__ src,
                                    float* __restrict__ cacheK, __half* __restrict__ Kr,
                                    float* __restrict__ cacheV, __half* __restrict__ Vr,
                                    const float* __restrict__ w) {
    int s = blockIdx.x;
    int h = blockIdx.y;
    int d = threadIdx.x;

    __shared__ float sh[HEAD_DIM];
    __shared__ float red[4];

    float x = src[(size_t)s * QKVDIM + QDIM + h * HEAD_DIM + d];

    float sq = x * x;
#pragma unroll
    for (int off = 16; off > 0; off >>= 1)
        sq += __shfl_down_sync(0xffffffff, sq, off);
    if ((d & 31) == 0) red[d >> 5] = sq;
    __syncthreads();
    float var = (red[0] + red[1] + red[2] + red[3]) * (1.0f / HEAD_DIM);
    float r = rsqrtf(var + EPS);
    float xn = x * r * w[d];
    sh[d] = xn;
    __syncthreads();

    int f = d & 63;
    float inv_freq = powf(ROPE_THETA, -((float)f) / 64.0f);
    float ang = (float)s * inv_freq;
    float c = cosf(ang), sn = sinf(ang);
    float out;
    if (d < 64) out = xn * c - sh[d + 64] * sn;
    else        out = xn * c + sh[d - 64] * sn;

    size_t idx = ((size_t)h * S + s) * HEAD_DIM + d;
    cacheK[idx] = out;
    Kr[idx] = __float2half_rn(out);

    float v = src[(size_t)s * QKVDIM + QDIM + KVDIM + h * HEAD_DIM + d];
    cacheV[idx] = v;
    Vr[idx] = __float2half_rn(v);
}

// ----------------------------------------------------------------------------
// Flash attention, fp16 mma + ldmatrix, QT=128 (256 threads, 8 warps 4x2).
// Halves K/V tile loads and softmax passes per output vs QT=64.
// smem (bytes):
//   Qs  half 128x136  @ 0       (34816)  row stride 272B
//   KV  K:64x136 / V^T:128x72   @ 34816  (18432)
//   Ps  f32  128x68   @ 53248   (34816)
//   Ph  half 128x72   @ 88064   (18432)  row stride 144B
//   mS/lS/corr f32[128] @ 106496/107008/107520
// total 108032 B -> 2 CTA/SM
// ----------------------------------------------------------------------------
#define FQT 128
#define FKT 64
#define F_QS 0
#define F_KV 34816
#define F_PS 53248
#define F_PH 88064
#define F_MS 106496
#define F_LS 107008
#define F_CS 107520
#define F_TOT 108032

__global__ __launch_bounds__(256) void flash_f16(const __half* __restrict__ Kr,
                                                 const __half* __restrict__ Vr) {
    extern __shared__ char fsc[];
    const uint32_t fsb = smem_u32(fsc);
    __half* Qs = (__half*)(fsc + F_QS);
    __half* KVh = (__half*)(fsc + F_KV);
    float* Ps = (float*)(fsc + F_PS);
    __half* Ph = (__half*)(fsc + F_PH);
    float* mS = (float*)(fsc + F_MS);
    float* lS = (float*)(fsc + F_LS);
    float* corrS = (float*)(fsc + F_CS);

    const int qTile = gridDim.x - 1 - blockIdx.x;   // heavy tiles first
    const int h = blockIdx.y;
    const int g = h >> 2;
    const int tid = threadIdx.x;
    const int warp = tid >> 5;
    const int lane = tid & 31;
    const int wm = warp >> 1;     // 0..3 (rows)
    const int wn = warp & 1;      // 0..1 (cols)
    const int r = lane >> 2;
    const int cc = lane & 3;
    const int qBase = qTile * FQT;
    const float scale = 0.08838834764831845f;

    const uint32_t lmrow = (lane & 15);
    const uint32_t lmk = (lane >> 4) * 16;

    if (tid < FQT) { mS[tid] = -INFINITY; lS[tid] = 0.0f; }

    // load Q tile (128 rows x 128 halfs), row stride 272B
#pragma unroll
    for (int i = 0; i < 8; i++) {
        int idx = tid + i * 256;
        int row = idx >> 4, ch = idx & 15;
        uint4 v = *(const uint4*)&g_Qh[(size_t)(qBase + row) * QDIM + h * HEAD_DIM + ch * 8];
        *(uint4*)((char*)Qs + row * 272 + ch * 16) = v;
    }

    float oacc[2][8][4];
#pragma unroll
    for (int mt = 0; mt < 2; mt++)
#pragma unroll
        for (int nt = 0; nt < 8; nt++)
#pragma unroll
            for (int i = 0; i < 4; i++) oacc[mt][nt][i] = 0.0f;

    __syncthreads();

    const uint32_t aQ0 = fsb + F_QS + (wm * 32 + lmrow) * 272 + lmk;
    const uint32_t bK0 = fsb + F_KV + (wn * 32 + lmrow) * 272 + lmk;
    const uint32_t aP0 = fsb + F_PH + (wm * 32 + lmrow) * 144 + lmk;
    const uint32_t bV0 = fsb + F_KV + (wn * 64 + lmrow) * 144 + lmk;

    const int nkt = 2 * qTile + 2;    // K tiles covering [0, qBase+128)

    for (int kt = 0; kt < nkt; kt++) {
        const int kBase = kt * FKT;

        // load K tile (64 x 128 halfs), stride 272B
#pragma unroll
        for (int i = 0; i < 4; i++) {
            int idx = tid + i * 256;
            int row = idx >> 4, ch = idx & 15;
            uint4 v = *(const uint4*)&Kr[((size_t)g * S + kBase + row) * HEAD_DIM + ch * 8];
            *(uint4*)((char*)KVh + row * 272 + ch * 16) = v;
        }
        __syncthreads();

        // S = Q K^T (128x64, k=128 -> 8 k16 steps), warp tile 32x32
        float sacc[2][4][4];
#pragma unroll
        for (int mt = 0; mt < 2; mt++)
#pragma unroll
            for (int nt = 0; nt < 4; nt++)
#pragma unroll
                for (int i = 0; i < 4; i++) sacc[mt][nt][i] = 0.0f;

#pragma unroll
        for (int ks = 0; ks < 8; ks++) {
            const uint32_t ko = ks * 32;
            unsigned af[2][4];
            ldsm_x4(af[0], aQ0 + ko);
            ldsm_x4(af[1], aQ0 + 16 * 272 + ko);
            unsigned bf[2][4];
            ldsm_x4(bf[0], bK0 + ko);
            ldsm_x4(bf[1], bK0 + 16 * 272 + ko);
#pragma unroll
            for (int mt = 0; mt < 2; mt++)
#pragma unroll
                for (int nt = 0; nt < 4; nt++) {
                    unsigned b[2] = { bf[nt >> 1][nt & 1], bf[nt >> 1][2 + (nt & 1)] };
                    mma_f16(sacc[mt][nt], af[mt], b);
                }
        }

        // write masked, scaled S to Ps (fp32)
#pragma unroll
        for (int mt = 0; mt < 2; mt++) {
#pragma unroll
            for (int nt = 0; nt < 4; nt++) {
                int row0 = wm * 32 + mt * 16 + r;
                int col0 = wn * 32 + nt * 8 + 2 * cc;
                int qi0 = qBase + row0, qi1 = qi0 + 8;
                int kj0 = kBase + col0, kj1 = kj0 + 1;
                Ps[row0 * 68 + col0]       = (kj0 <= qi0) ? sacc[mt][nt][0] * scale : -1e30f;
                Ps[row0 * 68 + col0 + 1]   = (kj1 <= qi0) ? sacc[mt][nt][1] * scale : -1e30f;
                Ps[(row0 + 8) * 68 + col0]     = (kj0 <= qi1) ? sacc[mt][nt][2] * scale : -1e30f;
                Ps[(row0 + 8) * 68 + col0 + 1] = (kj1 <= qi1) ? sacc[mt][nt][3] * scale : -1e30f;
            }
        }
        __syncthreads();

        // load V^T (128 dims x 64 s, row stride 144B) — K region dead now
#pragma unroll
        for (int i = 0; i < 4; i++) {
            int idx = tid + i * 256;
            int s = idx & 63, c4 = idx >> 6;    // c4: 0..15
            uint4 v = *(const uint4*)&Vr[((size_t)g * S + kBase + s) * HEAD_DIM + c4 * 8];
            const __half* hv = (const __half*)&v;
#pragma unroll
            for (int j = 0; j < 8; j++)
                KVh[(c4 * 8 + j) * 72 + s] = hv[j];
        }

        // online softmax (fp32), P stored fp16 into Ph. 256 thr over 128 rows.
        {
            int row = tid >> 1;
            int half_i = tid & 1;
            float* prow = &Ps[row * 68 + half_i * 32];
            __half* phrow = &Ph[row * 72 + half_i * 32];
            float mloc = -INFINITY;
#pragma unroll 8
            for (int j = 0; j < 32; j++) mloc = fmaxf(mloc, prow[j]);
            mloc = fmaxf(mloc, __shfl_xor_sync(0xffffffffu, mloc, 1));
            float mprev = mS[row];
            float mnew = fmaxf(mprev, mloc);
            float lsum = 0.0f;
#pragma unroll 8
            for (int j = 0; j < 32; j++) {
                float p = __expf(prow[j] - mnew);
                lsum += p;
                phrow[j] = __float2half_rn(p);
            }
            lsum += __shfl_xor_sync(0xffffffffu, lsum, 1);
            if (half_i == 0) {
                float corr = __expf(mprev - mnew);
                corrS[row] = corr;
                lS[row] = lS[row] * corr + lsum;
                mS[row] = mnew;
            }
        }
        __syncthreads();

        // rescale O accumulators
#pragma unroll
        for (int mt = 0; mt < 2; mt++) {
            int row0 = wm * 32 + mt * 16 + r;
            float cr0 = corrS[row0];
            float cr1 = corrS[row0 + 8];
#pragma unroll
            for (int nt = 0; nt < 8; nt++) {
                oacc[mt][nt][0] *= cr0; oacc[mt][nt][1] *= cr0;
                oacc[mt][nt][2] *= cr1; oacc[mt][nt][3] *= cr1;
            }
        }

        // O += P @ V (k=64 -> 4 k16 steps), warp tile 32x64
#pragma unroll
        for (int ks = 0; ks < 4; ks++) {
            const uint32_t ko = ks * 32;
            unsigned af[2][4];
            ldsm_x4(af[0], aP0 + ko);
            ldsm_x4(af[1], aP0 + 16 * 144 + ko);
            unsigned bf[4][4];
#pragma unroll
            for (int p = 0; p < 4; p++)
                ldsm_x4(bf[p], bV0 + p * 16 * 144 + ko);
#pragma unroll
            for (int mt = 0; mt < 2; mt++)
#pragma unroll
                for (int nt = 0; nt < 8; nt++) {
                    unsigned b[2] = { bf[nt >> 1][nt & 1], bf[nt >> 1][2 + (nt & 1)] };
                    mma_f16(oacc[mt][nt], af[mt], b);
                }
        }
        __syncthreads();
    }

    // epilogue: normalize, write fp16 O
#pragma unroll
    for (int mt = 0; mt < 2; mt++) {
        int row0 = wm * 32 + mt * 16 + r;
        float li0 = 1.0f / lS[row0];
        float li1 = 1.0f / lS[row0 + 8];
#pragma unroll
        for (int nt = 0; nt < 8; nt++) {
            int col = wn * 64 + nt * 8 + 2 * cc;
            __half2 v0 = __floats2half2_rn(oacc[mt][nt][0] * li0, oacc[mt][nt][1] * li0);
            __half2 v1 = __floats2half2_rn(oacc[mt][nt][2] * li1, oacc[mt][nt][3] * li1);
            *(unsigned*)&g_Oh[(size_t)(qBase + row0) * QDIM + h * HEAD_DIM + col] = *(unsigned*)&v0;
            *(unsigned*)&g_Oh[(size_t)(qBase + row0 + 8) * QDIM + h * HEAD_DIM + col] = *(unsigned*)&v1;
        }
    }
}

// ----------------------------------------------------------------------------
extern "C" void kernel_launch(void* const* d_in, const int* in_sizes, int n_in,
                              void* d_out, int out_size) {
    const float* x  = (const float*)d_in[0];
    const float* Wq = (const float*)d_in[1];
    const float* Wk = (const float*)d_in[2];
    const float* Wv = (const float*)d_in[3];
    const float* Wo = (const float*)d_in[4];
    const float* qw = (const float*)d_in[5];
    const float* kw = (const float*)d_in[6];

    float* out    = (float*)d_out;
    float* cacheK = out + (size_t)S * D_MODEL;
    float* cacheV = cacheK + (size_t)NUM_KV_HEADS * S * HEAD_DIM;

    __half* dXh;   cudaGetSymbolAddress((void**)&dXh, g_Xh);
    __half* dWqkvh;cudaGetSymbolAddress((void**)&dWqkvh, g_Wqkvh);
    __half* dWoh;  cudaGetSymbolAddress((void**)&dWoh, g_Woh);
    float*  dQKV;  cudaGetSymbolAddress((void**)&dQKV, g_QKV);
    __half* dQh;   cudaGetSymbolAddress((void**)&dQh, g_Qh);
    __half* dKrh;  cudaGetSymbolAddress((void**)&dKrh, g_Krh);
    __half* dVrh;  cudaGetSymbolAddress((void**)&dVrh, g_Vrh);
    __half* dOh;   cudaGetSymbolAddress((void**)&dOh, g_Oh);

    cudaFuncSetAttribute(gemm_f16, cudaFuncAttributeMaxDynamicSharedMemorySize, G4_SMEM);
    cudaFuncSetAttribute(gemm_f16_64, cudaFuncAttributeMaxDynamicSharedMemorySize, G5_SMEM);
    cudaFuncSetAttribute(flash_f16, cudaFuncAttributeMaxDynamicSharedMemorySize, F_TOT);

    // (1) convert all inputs to fp16
    round_all_kernel<<<(R_TOT + 255) / 256, 256>>>(x, Wq, Wk, Wv, Wo);

    // (2) fused QKV projection: [2048, 6144] = X @ [Wq;Wk;Wv]^T
    gemm_f16<<<dim3(QKVDIM / BN4, S / BM4), 128, G4_SMEM>>>(
        dXh, dWqkvh, dQKV, S, QKVDIM, D_MODEL, QKVDIM);

    // (3) Q norm+rope -> g_Qh
    norm_rope_q_kernel<<<dim3(S, NUM_HEADS), HEAD_DIM>>>(dQKV, dQh, qw);

    // (4) K norm+rope -> cache_k fp32 + g_Krh, V -> cache_v fp32 + g_Vrh
    norm_rope_kv_kernel<<<dim3(S, NUM_KV_HEADS), HEAD_DIM>>>(
        dQKV, cacheK, dKrh, cacheV, dVrh, kw);

    // (5) Flash attention: QT=128 tiles, heavy tiles scheduled first
    flash_f16<<<dim3(S / FQT, NUM_HEADS), 256, F_TOT>>>(dKrh, dVrh);

    // (6) Output projection: out = O @ Wo^T (64x64 tiles, 1280 blocks)
    gemm_f16_64<<<dim3(D_MODEL / BN5, S / BM5), 128, G5_SMEM>>>(
        dOh, dWoh, out, S, D_MODEL, QDIM, D_MODEL);
}

// round 13
// speedup vs baseline: 1.1739x; 1.1739x over previous
#include <cuda_runtime.h>
#include <cuda_fp16.h>
#include <math.h>
#include <stdint.h>

// Problem constants
#define S 2048
#define D_MODEL 2560
#define NUM_HEADS 32
#define NUM_KV_HEADS 8
#define HEAD_DIM 128
#define QDIM (NUM_HEADS * HEAD_DIM)     // 4096
#define KVDIM (NUM_KV_HEADS * HEAD_DIM) // 1024
#define QKVDIM (QDIM + 2 * KVDIM)       // 6144
#define EPS 1e-6f
#define ROPE_THETA 5000000.0f

// Scratch (no allocs allowed -> __device__ globals)
__device__ __half g_Xh[S * D_MODEL];
__device__ __half g_Wqkvh[QKVDIM * D_MODEL];
__device__ __half g_Woh[D_MODEL * QDIM];
__device__ float  g_QKV[S * QKVDIM];
__device__ __half g_Qh[S * QDIM];
__device__ __half g_Krh[NUM_KV_HEADS * S * HEAD_DIM];
__device__ __half g_Vrh[NUM_KV_HEADS * S * HEAD_DIM];
__device__ __half g_Oh[S * QDIM];

// ----------------------------------------------------------------------------
// helpers
// ----------------------------------------------------------------------------
__device__ __forceinline__ void mma_f16(float* d, const unsigned* a, const unsigned* b) {
    asm volatile(
        "mma.sync.aligned.m16n8k16.row.col.f32.f16.f16.f32 "
        "{%0,%1,%2,%3}, {%4,%5,%6,%7}, {%8,%9}, {%0,%1,%2,%3};"
        : "+f"(d[0]), "+f"(d[1]), "+f"(d[2]), "+f"(d[3])
        : "r"(a[0]), "r"(a[1]), "r"(a[2]), "r"(a[3]), "r"(b[0]), "r"(b[1]));
}

__device__ __forceinline__ void ldsm_x4(unsigned* r, uint32_t addr) {
    asm volatile("ldmatrix.sync.aligned.m8n8.x4.shared.b16 {%0,%1,%2,%3}, [%4];"
                 : "=r"(r[0]), "=r"(r[1]), "=r"(r[2]), "=r"(r[3]) : "r"(addr));
}

__device__ __forceinline__ void cp_async16(void* smem_dst, const void* gmem_src) {
    unsigned saddr = (unsigned)__cvta_generic_to_shared(smem_dst);
    asm volatile("cp.async.cg.shared.global [%0], [%1], 16;" :: "r"(saddr), "l"(gmem_src));
}
#define CP_COMMIT() asm volatile("cp.async.commit_group;")

__device__ __forceinline__ uint32_t smem_u32(const void* p) {
    uint32_t a;
    asm("{ .reg .u64 t; cvta.to.shared.u64 t, %1; cvt.u32.u64 %0, t; }" : "=r"(a) : "l"(p));
    return a;
}

__device__ __forceinline__ unsigned pack_h2(float a, float b) {
    __half2 h = __floats2half2_rn(a, b);
    return *(unsigned*)&h;
}

// ----------------------------------------------------------------------------
// Fused conversion of all inputs to fp16 (RNE). One launch.
// ----------------------------------------------------------------------------
#define R_N1 (S * D_MODEL / 4)
#define R_N2 (QDIM * D_MODEL / 4)
#define R_N3 (KVDIM * D_MODEL / 4)
#define R_TOT (R_N1 + R_N2 + 2 * R_N3 + R_N2)

__global__ void round_all_kernel(const float* __restrict__ x,
                                 const float* __restrict__ Wq,
                                 const float* __restrict__ Wk,
                                 const float* __restrict__ Wv,
                                 const float* __restrict__ Wo) {
    long i = (long)blockIdx.x * blockDim.x + threadIdx.x;
    if (i >= R_TOT) return;
    const float4* src;
    __half* dst;
    if (i < R_N1) {
        src = (const float4*)x;
        dst = g_Xh;
    } else if (i < R_N1 + R_N2) {
        i -= R_N1;
        src = (const float4*)Wq;
        dst = g_Wqkvh;
    } else if (i < R_N1 + R_N2 + R_N3) {
        i -= R_N1 + R_N2;
        src = (const float4*)Wk;
        dst = g_Wqkvh + (size_t)QDIM * D_MODEL;
    } else if (i < R_N1 + R_N2 + 2 * R_N3) {
        i -= R_N1 + R_N2 + R_N3;
        src = (const float4*)Wv;
        dst = g_Wqkvh + (size_t)(QDIM + KVDIM) * D_MODEL;
    } else {
        i -= R_N1 + R_N2 + 2 * R_N3;
        src = (const float4*)Wo;
        dst = g_Woh;
    }
    float4 v = src[i];
    __half2 h0 = __floats2half2_rn(v.x, v.y);
    __half2 h1 = __floats2half2_rn(v.z, v.w);
    uint2 pk = make_uint2(*(unsigned*)&h0, *(unsigned*)&h1);
    *(uint2*)&dst[i * 4] = pk;
}

// ----------------------------------------------------------------------------
// fp16 NT GEMM 128x64 (both projections). Proven R11 kernel, unchanged.
// ----------------------------------------------------------------------------
#define BM4 128
#define BN4 64
#define BK4 64
#define ROWB 144
#define STG4_B ((BM4 + BN4) * ROWB)       // 27648
#define G4_SMEM (2 * STG4_B)              // 55296

__global__ __launch_bounds__(128) void gemm_f16(const __half* __restrict__ A,
                                                const __half* __restrict__ B,
                                                float* __restrict__ C,
                                                int M, int N, int K, int ldc) {
    extern __shared__ char sm4[];
    const uint32_t sbase = smem_u32(sm4);

    const int tid = threadIdx.x;
    const int warp = tid >> 5;
    const int lane = tid & 31;
    const int r = lane >> 2;
    const int cc = lane & 3;
    const int bm0 = blockIdx.y * BM4;
    const int bn0 = blockIdx.x * BN4;
    const int nk = K / BK4;

    const uint32_t lmrow = (lane & 15);
    const uint32_t lmk = (lane >> 4) * 16;

    auto issue = [&](int kt) {
        char* As = sm4 + (kt & 1) * STG4_B;
        char* Bs = As + BM4 * ROWB;
        const int k0 = kt * BK4;
#pragma unroll
        for (int i = 0; i < 8; i++) {
            int task = tid + i * 128;
            int row = task >> 3, ch = task & 7;
            cp_async16(As + row * ROWB + ch * 16,
                       &A[(size_t)(bm0 + row) * K + k0 + ch * 8]);
        }
#pragma unroll
        for (int i = 0; i < 4; i++) {
            int task = tid + i * 128;
            int row = task >> 3, ch = task & 7;
            cp_async16(Bs + row * ROWB + ch * 16,
                       &B[(size_t)(bn0 + row) * K + k0 + ch * 8]);
        }
        CP_COMMIT();
    };

    issue(0);
    if (nk > 1) issue(1);

    float acc[2][8][4];
#pragma unroll
    for (int mt = 0; mt < 2; mt++)
#pragma unroll
        for (int nt = 0; nt < 8; nt++)
#pragma unroll
            for (int i = 0; i < 4; i++) acc[mt][nt][i] = 0.0f;

    for (int kt = 0; kt < nk; kt++) {
        if (kt == nk - 1) asm volatile("cp.async.wait_group 0;" ::: "memory");
        else              asm volatile("cp.async.wait_group 1;" ::: "memory");
        __syncthreads();

        const uint32_t stA = sbase + (kt & 1) * STG4_B;
        const uint32_t stB = stA + BM4 * ROWB;
        const uint32_t aAddr0 = stA + (warp * 32 + lmrow) * ROWB + lmk;
        const uint32_t bAddr0 = stB + lmrow * ROWB + lmk;

#pragma unroll
        for (int ks = 0; ks < 4; ks++) {
            const uint32_t ko = ks * 32;
            unsigned af[2][4];
            ldsm_x4(af[0], aAddr0 + ko);
            ldsm_x4(af[1], aAddr0 + 16 * ROWB + ko);
            unsigned bf[4][4];
#pragma unroll
            for (int p = 0; p < 4; p++)
                ldsm_x4(bf[p], bAddr0 + p * 16 * ROWB + ko);
#pragma unroll
            for (int mt = 0; mt < 2; mt++)
#pragma unroll
                for (int nt = 0; nt < 8; nt++) {
                    unsigned b[2] = { bf[nt >> 1][nt & 1], bf[nt >> 1][2 + (nt & 1)] };
                    mma_f16(acc[mt][nt], af[mt], b);
                }
        }
        __syncthreads();
        if (kt + 2 < nk) issue(kt + 2);
    }

#pragma unroll
    for (int mt = 0; mt < 2; mt++) {
#pragma unroll
        for (int nt = 0; nt < 8; nt++) {
            int row = bm0 + warp * 32 + mt * 16 + r;
            int col = bn0 + nt * 8 + 2 * cc;
            float2 v0 = make_float2(acc[mt][nt][0], acc[mt][nt][1]);
            float2 v1 = make_float2(acc[mt][nt][2], acc[mt][nt][3]);
            *(float2*)&C[(size_t)row * ldc + col] = v0;
            *(float2*)&C[(size_t)(row + 8) * ldc + col] = v1;
        }
    }
}

// ----------------------------------------------------------------------------
// RMSNorm + RoPE for Q (writes g_Qh fp16)
// ----------------------------------------------------------------------------
__global__ void norm_rope_q_kernel(const float* __restrict__ src, __half* __restrict__ dst,
                                   const float* __restrict__ w) {
    int s = blockIdx.x;
    int h = blockIdx.y;
    int d = threadIdx.x;

    __shared__ float sh[HEAD_DIM];
    __shared__ float red[4];

    float x = src[(size_t)s * QKVDIM + h * HEAD_DIM + d];

    float sq = x * x;
#pragma unroll
    for (int off = 16; off > 0; off >>= 1)
        sq += __shfl_down_sync(0xffffffff, sq, off);
    if ((d & 31) == 0) red[d >> 5] = sq;
    __syncthreads();
    float var = (red[0] + red[1] + red[2] + red[3]) * (1.0f / HEAD_DIM);
    float r = rsqrtf(var + EPS);
    float xn = x * r * w[d];
    sh[d] = xn;
    __syncthreads();

    int f = d & 63;
    float inv_freq = powf(ROPE_THETA, -((float)f) / 64.0f);
    float ang = (float)s * inv_freq;
    float c = cosf(ang), sn = sinf(ang);
    float out;
    if (d < 64) out = xn * c - sh[d + 64] * sn;
    else        out = xn * c + sh[d - 64] * sn;

    dst[(size_t)s * QDIM + h * HEAD_DIM + d] = __float2half_rn(out);
}

// ----------------------------------------------------------------------------
// RMSNorm + RoPE for K (-> cache_k fp32 + g_Krh fp16) AND V copy
// ----------------------------------------------------------------------------
__global__ void norm_rope_kv_kernel(const float* __restrict__ src,
                                    float* __restrict__ cacheK, __half* __restrict__ Kr,
                                    float* __restrict__ cacheV, __half* __restrict__ Vr,
                                    const float* __restrict__ w) {
    int s = blockIdx.x;
    int h = blockIdx.y;
    int d = threadIdx.x;

    __shared__ float sh[HEAD_DIM];
    __shared__ float red[4];

    float x = src[(size_t)s * QKVDIM + QDIM + h * HEAD_DIM + d];

    float sq = x * x;
#pragma unroll
    for (int off = 16; off > 0; off >>= 1)
        sq += __shfl_down_sync(0xffffffff, sq, off);
    if ((d & 31) == 0) red[d >> 5] = sq;
    __syncthreads();
    float var = (red[0] + red[1] + red[2] + red[3]) * (1.0f / HEAD_DIM);
    float r = rsqrtf(var + EPS);
    float xn = x * r * w[d];
    sh[d] = xn;
    __syncthreads();

    int f = d & 63;
    float inv_freq = powf(ROPE_THETA, -((float)f) / 64.0f);
    float ang = (float)s * inv_freq;
    float c = cosf(ang), sn = sinf(ang);
    float out;
    if (d < 64) out = xn * c - sh[d + 64] * sn;
    else        out = xn * c + sh[d - 64] * sn;

    size_t idx = ((size_t)h * S + s) * HEAD_DIM + d;
    cacheK[idx] = out;
    Kr[idx] = __float2half_rn(out);

    float v = src[(size_t)s * QKVDIM + QDIM + KVDIM + h * HEAD_DIM + d];
    cacheV[idx] = v;
    Vr[idx] = __float2half_rn(v);
}

// ----------------------------------------------------------------------------
// Flash attention v2: register-resident P (FA2 style). QT=64, 128 threads,
// 4 warps each owning 16 query rows x FULL 64-col K width. Softmax entirely
// in registers (shfl over the cc-quad); P accumulator fragments repacked as
// A-operands of the PV mma. No P smem, no stats smem, 3 syncs/tile.
// smem: Qs 64x272B @0 (17408) | KV: K 64x272B / V^T 128x144B @17408 (18432)
// total 35840 B.
// ----------------------------------------------------------------------------
#define FQT 64
#define FKT 64
#define F_QS 0
#define F_KV 17408
#define F_TOT 35840

__global__ __launch_bounds__(128) void flash_f16(const __half* __restrict__ Kr,
                                                 const __half* __restrict__ Vr) {
    extern __shared__ char fsc[];
    const uint32_t fsb = smem_u32(fsc);
    __half* Qs = (__half*)(fsc + F_QS);
    __half* KVh = (__half*)(fsc + F_KV);

    const int qTile = gridDim.x - 1 - blockIdx.x;   // heavy tiles first
    const int h = blockIdx.y;
    const int g = h >> 2;
    const int tid = threadIdx.x;
    const int warp = tid >> 5;        // 0..3 -> rows warp*16..+16
    const int lane = tid & 31;
    const int r = lane >> 2;
    const int cc = lane & 3;
    const int qBase = qTile * FQT;
    const float scale = 0.08838834764831845f;

    const uint32_t lmrow = (lane & 15);
    const uint32_t lmk = (lane >> 4) * 16;

    // load Q tile (64 x 128 halfs), row stride 272B
#pragma unroll
    for (int i = 0; i < 8; i++) {
        int idx = tid + i * 128;
        int row = idx >> 4, ch = idx & 15;
        uint4 v = *(const uint4*)&g_Qh[(size_t)(qBase + row) * QDIM + h * HEAD_DIM + ch * 8];
        *(uint4*)((char*)Qs + row * 272 + ch * 16) = v;
    }

    // O accumulators: 16 n8-tiles covering all 128 dims; rows warp*16 (+r, +8)
    float oacc[16][4];
#pragma unroll
    for (int nv = 0; nv < 16; nv++)
#pragma unroll
        for (int i = 0; i < 4; i++) oacc[nv][i] = 0.0f;

    // per-thread row stats (rows warp*16+r and +8), replicated across cc-quad
    float mst0 = -INFINITY, mst1 = -INFINITY, lst0 = 0.0f, lst1 = 0.0f;

    __syncthreads();

    const uint32_t aQ0 = fsb + F_QS + (warp * 16 + lmrow) * 272 + lmk;
    const uint32_t bK0 = fsb + F_KV + lmrow * 272 + lmk;
    const uint32_t bV0 = fsb + F_KV + lmrow * 144 + lmk;

    const int row0g = qBase + warp * 16 + r;
    const int row1g = row0g + 8;

    for (int kt = 0; kt <= qTile; kt++) {
        const int kBase = kt * FKT;

        // load K tile (64 x 128 halfs), stride 272B
#pragma unroll
        for (int i = 0; i < 8; i++) {
            int idx = tid + i * 128;
            int row = idx >> 4, ch = idx & 15;
            uint4 v = *(const uint4*)&Kr[((size_t)g * S + kBase + row) * HEAD_DIM + ch * 8];
            *(uint4*)((char*)KVh + row * 272 + ch * 16) = v;
        }
        __syncthreads();

        // S = Q K^T : warp tile 16 x 64 (8 n8-tiles), k=128 -> 8 k16 steps
        float sacc[8][4];
#pragma unroll
        for (int nt = 0; nt < 8; nt++)
#pragma unroll
            for (int i = 0; i < 4; i++) sacc[nt][i] = 0.0f;

#pragma unroll
        for (int ks = 0; ks < 8; ks++) {
            const uint32_t ko = ks * 32;
            unsigned af[4];
            ldsm_x4(af, aQ0 + ko);
            unsigned bf[4][4];
#pragma unroll
            for (int p = 0; p < 4; p++)
                ldsm_x4(bf[p], bK0 + p * 16 * 272 + ko);
#pragma unroll
            for (int nt = 0; nt < 8; nt++) {
                unsigned b[2] = { bf[nt >> 1][nt & 1], bf[nt >> 1][2 + (nt & 1)] };
                mma_f16(sacc[nt], af, b);
            }
        }
        __syncthreads();   // all warps done reading K fragments

        // load V^T (128 dims x 64 kv, row stride 144B) into same region
#pragma unroll
        for (int i = 0; i < 8; i++) {
            int idx = tid + i * 128;
            int s = idx & 63, c4 = idx >> 6;
            uint4 v = *(const uint4*)&Vr[((size_t)g * S + kBase + s) * HEAD_DIM + c4 * 8];
            const __half* hv = (const __half*)&v;
#pragma unroll
            for (int j = 0; j < 8; j++)
                KVh[(c4 * 8 + j) * 72 + s] = hv[j];
        }

        // ---- register softmax (overlaps V store latency) ----
        // mask + scale
#pragma unroll
        for (int nt = 0; nt < 8; nt++) {
            int c0 = kBase + nt * 8 + 2 * cc, c1 = c0 + 1;
            sacc[nt][0] = (c0 <= row0g) ? sacc[nt][0] * scale : -1e30f;
            sacc[nt][1] = (c1 <= row0g) ? sacc[nt][1] * scale : -1e30f;
            sacc[nt][2] = (c0 <= row1g) ? sacc[nt][2] * scale : -1e30f;
            sacc[nt][3] = (c1 <= row1g) ? sacc[nt][3] * scale : -1e30f;
        }
        // row maxes (exact, order-free)
        float m0l = -INFINITY, m1l = -INFINITY;
#pragma unroll
        for (int nt = 0; nt < 8; nt++) {
            m0l = fmaxf(m0l, fmaxf(sacc[nt][0], sacc[nt][1]));
            m1l = fmaxf(m1l, fmaxf(sacc[nt][2], sacc[nt][3]));
        }
        m0l = fmaxf(m0l, __shfl_xor_sync(0xffffffffu, m0l, 1));
        m0l = fmaxf(m0l, __shfl_xor_sync(0xffffffffu, m0l, 2));
        m1l = fmaxf(m1l, __shfl_xor_sync(0xffffffffu, m1l, 1));
        m1l = fmaxf(m1l, __shfl_xor_sync(0xffffffffu, m1l, 2));
        float mnew0 = fmaxf(mst0, m0l), mnew1 = fmaxf(mst1, m1l);
        float corr0 = __expf(mst0 - mnew0), corr1 = __expf(mst1 - mnew1);

        // exp, sum, pack P fragments
        unsigned ph[8][2];
        float ls0 = 0.0f, ls1 = 0.0f;
#pragma unroll
        for (int nt = 0; nt < 8; nt++) {
            float p0 = __expf(sacc[nt][0] - mnew0);
            float p1 = __expf(sacc[nt][1] - mnew0);
            float p2 = __expf(sacc[nt][2] - mnew1);
            float p3 = __expf(sacc[nt][3] - mnew1);
            ls0 += p0 + p1;
            ls1 += p2 + p3;
            ph[nt][0] = pack_h2(p0, p1);   // row r
            ph[nt][1] = pack_h2(p2, p3);   // row r+8
        }
        ls0 += __shfl_xor_sync(0xffffffffu, ls0, 1);
        ls0 += __shfl_xor_sync(0xffffffffu, ls0, 2);
        ls1 += __shfl_xor_sync(0xffffffffu, ls1, 1);
        ls1 += __shfl_xor_sync(0xffffffffu, ls1, 2);
        lst0 = lst0 * corr0 + ls0;
        lst1 = lst1 * corr1 + ls1;
        mst0 = mnew0;
        mst1 = mnew1;

        // rescale O accumulators
#pragma unroll
        for (int nv = 0; nv < 16; nv++) {
            oacc[nv][0] *= corr0; oacc[nv][1] *= corr0;
            oacc[nv][2] *= corr1; oacc[nv][3] *= corr1;
        }

        __syncthreads();   // V^T resident

        // O += P @ V : k = 64 kv -> 4 k16 steps; A from registers.
#pragma unroll
        for (int ks = 0; ks < 4; ks++) {
            const uint32_t ko = ks * 32;
            unsigned af[4] = { ph[2 * ks][0], ph[2 * ks][1],
                               ph[2 * ks + 1][0], ph[2 * ks + 1][1] };
            unsigned bf[8][4];
#pragma unroll
            for (int p = 0; p < 8; p++)
                ldsm_x4(bf[p], bV0 + p * 16 * 144 + ko);
#pragma unroll
            for (int nv = 0; nv < 16; nv++) {
                unsigned b[2] = { bf[nv >> 1][nv & 1], bf[nv >> 1][2 + (nv & 1)] };
                mma_f16(oacc[nv], af, b);
            }
        }
        __syncthreads();   // done reading V before next K overwrite
    }

    // epilogue: normalize, write fp16 O
    float li0 = 1.0f / lst0;
    float li1 = 1.0f / lst1;
#pragma unroll
    for (int nv = 0; nv < 16; nv++) {
        int col = nv * 8 + 2 * cc;
        unsigned v0 = pack_h2(oacc[nv][0] * li0, oacc[nv][1] * li0);
        unsigned v1 = pack_h2(oacc[nv][2] * li1, oacc[nv][3] * li1);
        *(unsigned*)&g_Oh[(size_t)row0g * QDIM + h * HEAD_DIM + col] = v0;
        *(unsigned*)&g_Oh[(size_t)row1g * QDIM + h * HEAD_DIM + col] = v1;
    }
}

// ----------------------------------------------------------------------------
extern "C" void kernel_launch(void* const* d_in, const int* in_sizes, int n_in,
                              void* d_out, int out_size) {
    const float* x  = (const float*)d_in[0];
    const float* Wq = (const float*)d_in[1];
    const float* Wk = (const float*)d_in[2];
    const float* Wv = (const float*)d_in[3];
    const float* Wo = (const float*)d_in[4];
    const float* qw = (const float*)d_in[5];
    const float* kw = (const float*)d_in[6];

    float* out    = (float*)d_out;
    float* cacheK = out + (size_t)S * D_MODEL;
    float* cacheV = cacheK + (size_t)NUM_KV_HEADS * S * HEAD_DIM;

    __half* dXh;   cudaGetSymbolAddress((void**)&dXh, g_Xh);
    __half* dWqkvh;cudaGetSymbolAddress((void**)&dWqkvh, g_Wqkvh);
    __half* dWoh;  cudaGetSymbolAddress((void**)&dWoh, g_Woh);
    float*  dQKV;  cudaGetSymbolAddress((void**)&dQKV, g_QKV);
    __half* dQh;   cudaGetSymbolAddress((void**)&dQh, g_Qh);
    __half* dKrh;  cudaGetSymbolAddress((void**)&dKrh, g_Krh);
    __half* dVrh;  cudaGetSymbolAddress((void**)&dVrh, g_Vrh);
    __half* dOh;   cudaGetSymbolAddress((void**)&dOh, g_Oh);

    cudaFuncSetAttribute(gemm_f16, cudaFuncAttributeMaxDynamicSharedMemorySize, G4_SMEM);
    cudaFuncSetAttribute(flash_f16, cudaFuncAttributeMaxDynamicSharedMemorySize, F_TOT);

    // (1) convert all inputs to fp16
    round_all_kernel<<<(R_TOT + 255) / 256, 256>>>(x, Wq, Wk, Wv, Wo);

    // (2) fused QKV projection: [2048, 6144] = X @ [Wq;Wk;Wv]^T
    gemm_f16<<<dim3(QKVDIM / BN4, S / BM4), 128, G4_SMEM>>>(
        dXh, dWqkvh, dQKV, S, QKVDIM, D_MODEL, QKVDIM);

    // (3) Q norm+rope -> g_Qh
    norm_rope_q_kernel<<<dim3(S, NUM_HEADS), HEAD_DIM>>>(dQKV, dQh, qw);

    // (4) K norm+rope -> cache_k fp32 + g_Krh, V -> cache_v fp32 + g_Vrh
    norm_rope_kv_kernel<<<dim3(S, NUM_KV_HEADS), HEAD_DIM>>>(
        dQKV, cacheK, dKrh, cacheV, dVrh, kw);

    // (5) Flash attention (register-resident P), heavy tiles first
    flash_f16<<<dim3(S / FQT, NUM_HEADS), 128, F_TOT>>>(dKrh, dVrh);

    // (6) Output projection: out = O @ Wo^T
    gemm_f16<<<dim3(D_MODEL / BN4, S / BM4), 128, G4_SMEM>>>(
        dOh, dWoh, out, S, D_MODEL, QDIM, D_MODEL);
}

// round 14
// speedup vs baseline: 1.2064x; 1.0277x over previous
#include <cuda_runtime.h>
#include <cuda_fp16.h>
#include <math.h>
#include <stdint.h>

// Problem constants
#define S 2048
#define D_MODEL 2560
#define NUM_HEADS 32
#define NUM_KV_HEADS 8
#define HEAD_DIM 128
#define QDIM (NUM_HEADS * HEAD_DIM)     // 4096
#define KVDIM (NUM_KV_HEADS * HEAD_DIM) // 1024
#define QKVDIM (QDIM + 2 * KVDIM)       // 6144
#define EPS 1e-6f
#define ROPE_THETA 5000000.0f

// Scratch (no allocs allowed -> __device__ globals)
__device__ __half g_Xh[S * D_MODEL];
__device__ __half g_Wqkvh[QKVDIM * D_MODEL];
__device__ __half g_Woh[D_MODEL * QDIM];
__device__ float  g_QKV[S * QKVDIM];
__device__ __half g_Qh[S * QDIM];
__device__ __half g_Krh[NUM_KV_HEADS * S * HEAD_DIM];
__device__ __half g_Vrh[NUM_KV_HEADS * S * HEAD_DIM];
__device__ __half g_Oh[S * QDIM];

// ----------------------------------------------------------------------------
// helpers
// ----------------------------------------------------------------------------
__device__ __forceinline__ void mma_f16(float* d, const unsigned* a, const unsigned* b) {
    asm volatile(
        "mma.sync.aligned.m16n8k16.row.col.f32.f16.f16.f32 "
        "{%0,%1,%2,%3}, {%4,%5,%6,%7}, {%8,%9}, {%0,%1,%2,%3};"
        : "+f"(d[0]), "+f"(d[1]), "+f"(d[2]), "+f"(d[3])
        : "r"(a[0]), "r"(a[1]), "r"(a[2]), "r"(a[3]), "r"(b[0]), "r"(b[1]));
}

__device__ __forceinline__ void ldsm_x4(unsigned* r, uint32_t addr) {
    asm volatile("ldmatrix.sync.aligned.m8n8.x4.shared.b16 {%0,%1,%2,%3}, [%4];"
                 : "=r"(r[0]), "=r"(r[1]), "=r"(r[2]), "=r"(r[3]) : "r"(addr));
}

__device__ __forceinline__ void cp_async16(void* smem_dst, const void* gmem_src) {
    unsigned saddr = (unsigned)__cvta_generic_to_shared(smem_dst);
    asm volatile("cp.async.cg.shared.global [%0], [%1], 16;" :: "r"(saddr), "l"(gmem_src));
}
#define CP_COMMIT() asm volatile("cp.async.commit_group;")

__device__ __forceinline__ uint32_t smem_u32(const void* p) {
    uint32_t a;
    asm("{ .reg .u64 t; cvta.to.shared.u64 t, %1; cvt.u32.u64 %0, t; }" : "=r"(a) : "l"(p));
    return a;
}

__device__ __forceinline__ unsigned pack_h2(float a, float b) {
    __half2 h = __floats2half2_rn(a, b);
    return *(unsigned*)&h;
}

// two exponentials (base 2) in one MUFU op
__device__ __forceinline__ unsigned ex2_h2(float a, float b) {
    __half2 h = __floats2half2_rn(a, b);
    unsigned in = *(unsigned*)&h, out;
    asm("ex2.approx.f16x2 %0, %1;" : "=r"(out) : "r"(in));
    return out;
}

// ----------------------------------------------------------------------------
// Fused conversion of all inputs to fp16 (RNE). One launch.
// ----------------------------------------------------------------------------
#define R_N1 (S * D_MODEL / 4)
#define R_N2 (QDIM * D_MODEL / 4)
#define R_N3 (KVDIM * D_MODEL / 4)
#define R_TOT (R_N1 + R_N2 + 2 * R_N3 + R_N2)

__global__ void round_all_kernel(const float* __restrict__ x,
                                 const float* __restrict__ Wq,
                                 const float* __restrict__ Wk,
                                 const float* __restrict__ Wv,
                                 const float* __restrict__ Wo) {
    long i = (long)blockIdx.x * blockDim.x + threadIdx.x;
    if (i >= R_TOT) return;
    const float4* src;
    __half* dst;
    if (i < R_N1) {
        src = (const float4*)x;
        dst = g_Xh;
    } else if (i < R_N1 + R_N2) {
        i -= R_N1;
        src = (const float4*)Wq;
        dst = g_Wqkvh;
    } else if (i < R_N1 + R_N2 + R_N3) {
        i -= R_N1 + R_N2;
        src = (const float4*)Wk;
        dst = g_Wqkvh + (size_t)QDIM * D_MODEL;
    } else if (i < R_N1 + R_N2 + 2 * R_N3) {
        i -= R_N1 + R_N2 + R_N3;
        src = (const float4*)Wv;
        dst = g_Wqkvh + (size_t)(QDIM + KVDIM) * D_MODEL;
    } else {
        i -= R_N1 + R_N2 + 2 * R_N3;
        src = (const float4*)Wo;
        dst = g_Woh;
    }
    float4 v = src[i];
    __half2 h0 = __floats2half2_rn(v.x, v.y);
    __half2 h1 = __floats2half2_rn(v.z, v.w);
    uint2 pk = make_uint2(*(unsigned*)&h0, *(unsigned*)&h1);
    *(uint2*)&dst[i * 4] = pk;
}

// ----------------------------------------------------------------------------
// fp16 NT GEMM 128x64 (QKV projection). Proven R11/R13 kernel, unchanged.
// ----------------------------------------------------------------------------
#define BM4 128
#define BN4 64
#define BK4 64
#define ROWB 144
#define STG4_B ((BM4 + BN4) * ROWB)       // 27648
#define G4_SMEM (2 * STG4_B)              // 55296

__global__ __launch_bounds__(128) void gemm_f16(const __half* __restrict__ A,
                                                const __half* __restrict__ B,
                                                float* __restrict__ C,
                                                int M, int N, int K, int ldc) {
    extern __shared__ char sm4[];
    const uint32_t sbase = smem_u32(sm4);

    const int tid = threadIdx.x;
    const int warp = tid >> 5;
    const int lane = tid & 31;
    const int r = lane >> 2;
    const int cc = lane & 3;
    const int bm0 = blockIdx.y * BM4;
    const int bn0 = blockIdx.x * BN4;
    const int nk = K / BK4;

    const uint32_t lmrow = (lane & 15);
    const uint32_t lmk = (lane >> 4) * 16;

    auto issue = [&](int kt) {
        char* As = sm4 + (kt & 1) * STG4_B;
        char* Bs = As + BM4 * ROWB;
        const int k0 = kt * BK4;
#pragma unroll
        for (int i = 0; i < 8; i++) {
            int task = tid + i * 128;
            int row = task >> 3, ch = task & 7;
            cp_async16(As + row * ROWB + ch * 16,
                       &A[(size_t)(bm0 + row) * K + k0 + ch * 8]);
        }
#pragma unroll
        for (int i = 0; i < 4; i++) {
            int task = tid + i * 128;
            int row = task >> 3, ch = task & 7;
            cp_async16(Bs + row * ROWB + ch * 16,
                       &B[(size_t)(bn0 + row) * K + k0 + ch * 8]);
        }
        CP_COMMIT();
    };

    issue(0);
    if (nk > 1) issue(1);

    float acc[2][8][4];
#pragma unroll
    for (int mt = 0; mt < 2; mt++)
#pragma unroll
        for (int nt = 0; nt < 8; nt++)
#pragma unroll
            for (int i = 0; i < 4; i++) acc[mt][nt][i] = 0.0f;

    for (int kt = 0; kt < nk; kt++) {
        if (kt == nk - 1) asm volatile("cp.async.wait_group 0;" ::: "memory");
        else              asm volatile("cp.async.wait_group 1;" ::: "memory");
        __syncthreads();

        const uint32_t stA = sbase + (kt & 1) * STG4_B;
        const uint32_t stB = stA + BM4 * ROWB;
        const uint32_t aAddr0 = stA + (warp * 32 + lmrow) * ROWB + lmk;
        const uint32_t bAddr0 = stB + lmrow * ROWB + lmk;

#pragma unroll
        for (int ks = 0; ks < 4; ks++) {
            const uint32_t ko = ks * 32;
            unsigned af[2][4];
            ldsm_x4(af[0], aAddr0 + ko);
            ldsm_x4(af[1], aAddr0 + 16 * ROWB + ko);
            unsigned bf[4][4];
#pragma unroll
            for (int p = 0; p < 4; p++)
                ldsm_x4(bf[p], bAddr0 + p * 16 * ROWB + ko);
#pragma unroll
            for (int mt = 0; mt < 2; mt++)
#pragma unroll
                for (int nt = 0; nt < 8; nt++) {
                    unsigned b[2] = { bf[nt >> 1][nt & 1], bf[nt >> 1][2 + (nt & 1)] };
                    mma_f16(acc[mt][nt], af[mt], b);
                }
        }
        __syncthreads();
        if (kt + 2 < nk) issue(kt + 2);
    }

#pragma unroll
    for (int mt = 0; mt < 2; mt++) {
#pragma unroll
        for (int nt = 0; nt < 8; nt++) {
            int row = bm0 + warp * 32 + mt * 16 + r;
            int col = bn0 + nt * 8 + 2 * cc;
            float2 v0 = make_float2(acc[mt][nt][0], acc[mt][nt][1]);
            float2 v1 = make_float2(acc[mt][nt][2], acc[mt][nt][3]);
            *(float2*)&C[(size_t)row * ldc + col] = v0;
            *(float2*)&C[(size_t)(row + 8) * ldc + col] = v1;
        }
    }
}

// ----------------------------------------------------------------------------
// fp16 NT GEMM 64x64 (output projection): finer tiles for wave fit
// (1280 blocks @ ~6 CTA/SM vs 640 @ 4). Same k-order -> identical numerics.
// ----------------------------------------------------------------------------
#define BM5 64
#define BN5 64
#define STG5_B ((BM5 + BN5) * ROWB)       // 18432
#define G5_SMEM (2 * STG5_B)              // 36864

__global__ __launch_bounds__(128) void gemm_f16_64(const __half* __restrict__ A,
                                                   const __half* __restrict__ B,
                                                   float* __restrict__ C,
                                                   int M, int N, int K, int ldc) {
    extern __shared__ char sm5[];
    const uint32_t sbase = smem_u32(sm5);

    const int tid = threadIdx.x;
    const int warp = tid >> 5;
    const int lane = tid & 31;
    const int wm = warp >> 1;
    const int wn = warp & 1;
    const int r = lane >> 2;
    const int cc = lane & 3;
    const int bm0 = blockIdx.y * BM5;
    const int bn0 = blockIdx.x * BN5;
    const int nk = K / BK4;

    const uint32_t lmrow = (lane & 15);
    const uint32_t lmk = (lane >> 4) * 16;

    auto issue = [&](int kt) {
        char* As = sm5 + (kt & 1) * STG5_B;
        char* Bs = As + BM5 * ROWB;
        const int k0 = kt * BK4;
#pragma unroll
        for (int i = 0; i < 4; i++) {
            int task = tid + i * 128;
            int row = task >> 3, ch = task & 7;
            cp_async16(As + row * ROWB + ch * 16,
                       &A[(size_t)(bm0 + row) * K + k0 + ch * 8]);
        }
#pragma unroll
        for (int i = 0; i < 4; i++) {
            int task = tid + i * 128;
            int row = task >> 3, ch = task & 7;
            cp_async16(Bs + row * ROWB + ch * 16,
                       &B[(size_t)(bn0 + row) * K + k0 + ch * 8]);
        }
        CP_COMMIT();
    };

    issue(0);
    if (nk > 1) issue(1);

    float acc[2][4][4];
#pragma unroll
    for (int mt = 0; mt < 2; mt++)
#pragma unroll
        for (int nt = 0; nt < 4; nt++)
#pragma unroll
            for (int i = 0; i < 4; i++) acc[mt][nt][i] = 0.0f;

    for (int kt = 0; kt < nk; kt++) {
        if (kt == nk - 1) asm volatile("cp.async.wait_group 0;" ::: "memory");
        else              asm volatile("cp.async.wait_group 1;" ::: "memory");
        __syncthreads();

        const uint32_t stA = sbase + (kt & 1) * STG5_B;
        const uint32_t stB = stA + BM5 * ROWB;
        const uint32_t aAddr0 = stA + (wm * 32 + lmrow) * ROWB + lmk;
        const uint32_t bAddr0 = stB + (wn * 32 + lmrow) * ROWB + lmk;

#pragma unroll
        for (int ks = 0; ks < 4; ks++) {
            const uint32_t ko = ks * 32;
            unsigned af[2][4];
            ldsm_x4(af[0], aAddr0 + ko);
            ldsm_x4(af[1], aAddr0 + 16 * ROWB + ko);
            unsigned bf[2][4];
            ldsm_x4(bf[0], bAddr0 + ko);
            ldsm_x4(bf[1], bAddr0 + 16 * ROWB + ko);
#pragma unroll
            for (int mt = 0; mt < 2; mt++)
#pragma unroll
                for (int nt = 0; nt < 4; nt++) {
                    unsigned b[2] = { bf[nt >> 1][nt & 1], bf[nt >> 1][2 + (nt & 1)] };
                    mma_f16(acc[mt][nt], af[mt], b);
                }
        }
        __syncthreads();
        if (kt + 2 < nk) issue(kt + 2);
    }

#pragma unroll
    for (int mt = 0; mt < 2; mt++) {
#pragma unroll
        for (int nt = 0; nt < 4; nt++) {
            int row = bm0 + wm * 32 + mt * 16 + r;
            int col = bn0 + wn * 32 + nt * 8 + 2 * cc;
            float2 v0 = make_float2(acc[mt][nt][0], acc[mt][nt][1]);
            float2 v1 = make_float2(acc[mt][nt][2], acc[mt][nt][3]);
            *(float2*)&C[(size_t)row * ldc + col] = v0;
            *(float2*)&C[(size_t)(row + 8) * ldc + col] = v1;
        }
    }
}

// ----------------------------------------------------------------------------
// RMSNorm + RoPE for Q (writes g_Qh fp16)
// ----------------------------------------------------------------------------
__global__ void norm_rope_q_kernel(const float* __restrict__ src, __half* __restrict__ dst,
                                   const float* __restrict__ w) {
    int s = blockIdx.x;
    int h = blockIdx.y;
    int d = threadIdx.x;

    __shared__ float sh[HEAD_DIM];
    __shared__ float red[4];

    float x = src[(size_t)s * QKVDIM + h * HEAD_DIM + d];

    float sq = x * x;
#pragma unroll
    for (int off = 16; off > 0; off >>= 1)
        sq += __shfl_down_sync(0xffffffff, sq, off);
    if ((d & 31) == 0) red[d >> 5] = sq;
    __syncthreads();
    float var = (red[0] + red[1] + red[2] + red[3]) * (1.0f / HEAD_DIM);
    float r = rsqrtf(var + EPS);
    float xn = x * r * w[d];
    sh[d] = xn;
    __syncthreads();

    int f = d & 63;
    float inv_freq = powf(ROPE_THETA, -((float)f) / 64.0f);
    float ang = (float)s * inv_freq;
    float c = cosf(ang), sn = sinf(ang);
    float out;
    if (d < 64) out = xn * c - sh[d + 64] * sn;
    else        out = xn * c + sh[d - 64] * sn;

    dst[(size_t)s * QDIM + h * HEAD_DIM + d] = __float2half_rn(out);
}

// ----------------------------------------------------------------------------
// RMSNorm + RoPE for K (-> cache_k fp32 + g_Krh fp16) AND V copy
// ----------------------------------------------------------------------------
__global__ void norm_rope_kv_kernel(const float* __restrict__ src,
                                    float* __restrict__ cacheK, __half* __restrict__ Kr,
                                    float* __restrict__ cacheV, __half* __restrict__ Vr,
                                    const float* __restrict__ w) {
    int s = blockIdx.x;
    int h = blockIdx.y;
    int d = threadIdx.x;

    __shared__ float sh[HEAD_DIM];
    __shared__ float red[4];

    float x = src[(size_t)s * QKVDIM + QDIM + h * HEAD_DIM + d];

    float sq = x * x;
#pragma unroll
    for (int off = 16; off > 0; off >>= 1)
        sq += __shfl_down_sync(0xffffffff, sq, off);
    if ((d & 31) == 0) red[d >> 5] = sq;
    __syncthreads();
    float var = (red[0] + red[1] + red[2] + red[3]) * (1.0f / HEAD_DIM);
    float r = rsqrtf(var + EPS);
    float xn = x * r * w[d];
    sh[d] = xn;
    __syncthreads();

    int f = d & 63;
    float inv_freq = powf(ROPE_THETA, -((float)f) / 64.0f);
    float ang = (float)s * inv_freq;
    float c = cosf(ang), sn = sinf(ang);
    float out;
    if (d < 64) out = xn * c - sh[d + 64] * sn;
    else        out = xn * c + sh[d - 64] * sn;

    size_t idx = ((size_t)h * S + s) * HEAD_DIM + d;
    cacheK[idx] = out;
    Kr[idx] = __float2half_rn(out);

    float v = src[(size_t)s * QKVDIM + QDIM + KVDIM + h * HEAD_DIM + d];
    cacheV[idx] = v;
    Vr[idx] = __float2half_rn(v);
}

// ----------------------------------------------------------------------------
// Flash attention v3: register-resident P + ex2.approx.f16x2 softmax
// (2 exponentials per MUFU op). Structure identical to R13 otherwise.
// smem: Qs 64x272B @0 (17408) | KV: K 64x272B / V^T 128x144B @17408 (18432)
// total 35840 B.
// ----------------------------------------------------------------------------
#define FQT 64
#define FKT 64
#define F_QS 0
#define F_KV 17408
#define F_TOT 35840

__global__ __launch_bounds__(128) void flash_f16(const __half* __restrict__ Kr,
                                                 const __half* __restrict__ Vr) {
    extern __shared__ char fsc[];
    const uint32_t fsb = smem_u32(fsc);
    __half* Qs = (__half*)(fsc + F_QS);
    __half* KVh = (__half*)(fsc + F_KV);

    const int qTile = gridDim.x - 1 - blockIdx.x;   // heavy tiles first
    const int h = blockIdx.y;
    const int g = h >> 2;
    const int tid = threadIdx.x;
    const int warp = tid >> 5;        // 0..3 -> rows warp*16..+16
    const int lane = tid & 31;
    const int r = lane >> 2;
    const int cc = lane & 3;
    const int qBase = qTile * FQT;
    const float scale = 0.08838834764831845f;
    const float sl2e = scale * 1.4426950408889634f;   // scale * log2(e)

    const uint32_t lmrow = (lane & 15);
    const uint32_t lmk = (lane >> 4) * 16;

    // load Q tile (64 x 128 halfs), row stride 272B
#pragma unroll
    for (int i = 0; i < 8; i++) {
        int idx = tid + i * 128;
        int row = idx >> 4, ch = idx & 15;
        uint4 v = *(const uint4*)&g_Qh[(size_t)(qBase + row) * QDIM + h * HEAD_DIM + ch * 8];
        *(uint4*)((char*)Qs + row * 272 + ch * 16) = v;
    }

    float oacc[16][4];
#pragma unroll
    for (int nv = 0; nv < 16; nv++)
#pragma unroll
        for (int i = 0; i < 4; i++) oacc[nv][i] = 0.0f;

    // running stats in RAW score units (rows warp*16+r and +8)
    float mst0 = -INFINITY, mst1 = -INFINITY, lst0 = 0.0f, lst1 = 0.0f;

    __syncthreads();

    const uint32_t aQ0 = fsb + F_QS + (warp * 16 + lmrow) * 272 + lmk;
    const uint32_t bK0 = fsb + F_KV + lmrow * 272 + lmk;
    const uint32_t bV0 = fsb + F_KV + lmrow * 144 + lmk;

    const int row0g = qBase + warp * 16 + r;
    const int row1g = row0g + 8;

    for (int kt = 0; kt <= qTile; kt++) {
        const int kBase = kt * FKT;

        // load K tile (64 x 128 halfs), stride 272B
#pragma unroll
        for (int i = 0; i < 8; i++) {
            int idx = tid + i * 128;
            int row = idx >> 4, ch = idx & 15;
            uint4 v = *(const uint4*)&Kr[((size_t)g * S + kBase + row) * HEAD_DIM + ch * 8];
            *(uint4*)((char*)KVh + row * 272 + ch * 16) = v;
        }
        __syncthreads();

        // S = Q K^T : warp tile 16 x 64, k=128 -> 8 k16 steps
        float sacc[8][4];
#pragma unroll
        for (int nt = 0; nt < 8; nt++)
#pragma unroll
            for (int i = 0; i < 4; i++) sacc[nt][i] = 0.0f;

#pragma unroll
        for (int ks = 0; ks < 8; ks++) {
            const uint32_t ko = ks * 32;
            unsigned af[4];
            ldsm_x4(af, aQ0 + ko);
            unsigned bf[4][4];
#pragma unroll
            for (int p = 0; p < 4; p++)
                ldsm_x4(bf[p], bK0 + p * 16 * 272 + ko);
#pragma unroll
            for (int nt = 0; nt < 8; nt++) {
                unsigned b[2] = { bf[nt >> 1][nt & 1], bf[nt >> 1][2 + (nt & 1)] };
                mma_f16(sacc[nt], af, b);
            }
        }
        __syncthreads();   // all warps done reading K fragments

        // load V^T (128 dims x 64 kv, row stride 144B) into same region
#pragma unroll
        for (int i = 0; i < 8; i++) {
            int idx = tid + i * 128;
            int s = idx & 63, c4 = idx >> 6;
            uint4 v = *(const uint4*)&Vr[((size_t)g * S + kBase + s) * HEAD_DIM + c4 * 8];
            const __half* hv = (const __half*)&v;
#pragma unroll
            for (int j = 0; j < 8; j++)
                KVh[(c4 * 8 + j) * 72 + s] = hv[j];
        }

        // ---- register softmax (base-2, fp16x2 exp) ----
        // mask (raw scores)
#pragma unroll
        for (int nt = 0; nt < 8; nt++) {
            int c0 = kBase + nt * 8 + 2 * cc, c1 = c0 + 1;
            if (c0 > row0g) sacc[nt][0] = -1e30f;
            if (c1 > row0g) sacc[nt][1] = -1e30f;
            if (c0 > row1g) sacc[nt][2] = -1e30f;
            if (c1 > row1g) sacc[nt][3] = -1e30f;
        }
        // raw row maxes (order-free)
        float m0l = -INFINITY, m1l = -INFINITY;
#pragma unroll
        for (int nt = 0; nt < 8; nt++) {
            m0l = fmaxf(m0l, fmaxf(sacc[nt][0], sacc[nt][1]));
            m1l = fmaxf(m1l, fmaxf(sacc[nt][2], sacc[nt][3]));
        }
        m0l = fmaxf(m0l, __shfl_xor_sync(0xffffffffu, m0l, 1));
        m0l = fmaxf(m0l, __shfl_xor_sync(0xffffffffu, m0l, 2));
        m1l = fmaxf(m1l, __shfl_xor_sync(0xffffffffu, m1l, 1));
        m1l = fmaxf(m1l, __shfl_xor_sync(0xffffffffu, m1l, 2));
        float mnew0 = fmaxf(mst0, m0l), mnew1 = fmaxf(mst1, m1l);
        float corr0 = __expf((mst0 - mnew0) * scale);
        float corr1 = __expf((mst1 - mnew1) * scale);

        // exp2 of scaled args, two at a time in fp16; sum l in fp32
        unsigned ph[8][2];
        float ls0 = 0.0f, ls1 = 0.0f;
#pragma unroll
        for (int nt = 0; nt < 8; nt++) {
            ph[nt][0] = ex2_h2((sacc[nt][0] - mnew0) * sl2e,
                               (sacc[nt][1] - mnew0) * sl2e);
            ph[nt][1] = ex2_h2((sacc[nt][2] - mnew1) * sl2e,
                               (sacc[nt][3] - mnew1) * sl2e);
            float2 p0 = __half22float2(*(__half2*)&ph[nt][0]);
            float2 p1 = __half22float2(*(__half2*)&ph[nt][1]);
            ls0 += p0.x + p0.y;
            ls1 += p1.x + p1.y;
        }
        ls0 += __shfl_xor_sync(0xffffffffu, ls0, 1);
        ls0 += __shfl_xor_sync(0xffffffffu, ls0, 2);
        ls1 += __shfl_xor_sync(0xffffffffu, ls1, 1);
        ls1 += __shfl_xor_sync(0xffffffffu, ls1, 2);
        lst0 = lst0 * corr0 + ls0;
        lst1 = lst1 * corr1 + ls1;
        mst0 = mnew0;
        mst1 = mnew1;

        // rescale O accumulators
#pragma unroll
        for (int nv = 0; nv < 16; nv++) {
            oacc[nv][0] *= corr0; oacc[nv][1] *= corr0;
            oacc[nv][2] *= corr1; oacc[nv][3] *= corr1;
        }

        __syncthreads();   // V^T resident

        // O += P @ V : 4 k16 steps; A (P) from registers.
#pragma unroll
        for (int ks = 0; ks < 4; ks++) {
            const uint32_t ko = ks * 32;
            unsigned af[4] = { ph[2 * ks][0], ph[2 * ks][1],
                               ph[2 * ks + 1][0], ph[2 * ks + 1][1] };
            unsigned bf[8][4];
#pragma unroll
            for (int p = 0; p < 8; p++)
                ldsm_x4(bf[p], bV0 + p * 16 * 144 + ko);
#pragma unroll
            for (int nv = 0; nv < 16; nv++) {
                unsigned b[2] = { bf[nv >> 1][nv & 1], bf[nv >> 1][2 + (nv & 1)] };
                mma_f16(oacc[nv], af, b);
            }
        }
        __syncthreads();   // done reading V before next K overwrite
    }

    // epilogue: normalize, write fp16 O
    float li0 = 1.0f / lst0;
    float li1 = 1.0f / lst1;
#pragma unroll
    for (int nv = 0; nv < 16; nv++) {
        int col = nv * 8 + 2 * cc;
        unsigned v0 = pack_h2(oacc[nv][0] * li0, oacc[nv][1] * li0);
        unsigned v1 = pack_h2(oacc[nv][2] * li1, oacc[nv][3] * li1);
        *(unsigned*)&g_Oh[(size_t)row0g * QDIM + h * HEAD_DIM + col] = v0;
        *(unsigned*)&g_Oh[(size_t)row1g * QDIM + h * HEAD_DIM + col] = v1;
    }
}

// ----------------------------------------------------------------------------
extern "C" void kernel_launch(void* const* d_in, const int* in_sizes, int n_in,
                              void* d_out, int out_size) {
    const float* x  = (const float*)d_in[0];
    const float* Wq = (const float*)d_in[1];
    const float* Wk = (const float*)d_in[2];
    const float* Wv = (const float*)d_in[3];
    const float* Wo = (const float*)d_in[4];
    const float* qw = (const float*)d_in[5];
    const float* kw = (const float*)d_in[6];

    float* out    = (float*)d_out;
    float* cacheK = out + (size_t)S * D_MODEL;
    float* cacheV = cacheK + (size_t)NUM_KV_HEADS * S * HEAD_DIM;

    __half* dXh;   cudaGetSymbolAddress((void**)&dXh, g_Xh);
    __half* dWqkvh;cudaGetSymbolAddress((void**)&dWqkvh, g_Wqkvh);
    __half* dWoh;  cudaGetSymbolAddress((void**)&dWoh, g_Woh);
    float*  dQKV;  cudaGetSymbolAddress((void**)&dQKV, g_QKV);
    __half* dQh;   cudaGetSymbolAddress((void**)&dQh, g_Qh);
    __half* dKrh;  cudaGetSymbolAddress((void**)&dKrh, g_Krh);
    __half* dVrh;  cudaGetSymbolAddress((void**)&dVrh, g_Vrh);
    __half* dOh;   cudaGetSymbolAddress((void**)&dOh, g_Oh);

    cudaFuncSetAttribute(gemm_f16, cudaFuncAttributeMaxDynamicSharedMemorySize, G4_SMEM);
    cudaFuncSetAttribute(gemm_f16_64, cudaFuncAttributeMaxDynamicSharedMemorySize, G5_SMEM);
    cudaFuncSetAttribute(flash_f16, cudaFuncAttributeMaxDynamicSharedMemorySize, F_TOT);

    // (1) convert all inputs to fp16
    round_all_kernel<<<(R_TOT + 255) / 256, 256>>>(x, Wq, Wk, Wv, Wo);

    // (2) fused QKV projection: [2048, 6144] = X @ [Wq;Wk;Wv]^T
    gemm_f16<<<dim3(QKVDIM / BN4, S / BM4), 128, G4_SMEM>>>(
        dXh, dWqkvh, dQKV, S, QKVDIM, D_MODEL, QKVDIM);

    // (3) Q norm+rope -> g_Qh
    norm_rope_q_kernel<<<dim3(S, NUM_HEADS), HEAD_DIM>>>(dQKV, dQh, qw);

    // (4) K norm+rope -> cache_k fp32 + g_Krh, V -> cache_v fp32 + g_Vrh
    norm_rope_kv_kernel<<<dim3(S, NUM_KV_HEADS), HEAD_DIM>>>(
        dQKV, cacheK, dKrh, cacheV, dVrh, kw);

    // (5) Flash attention (register P + f16x2 exp), heavy tiles first
    flash_f16<<<dim3(S / FQT, NUM_HEADS), 128, F_TOT>>>(dKrh, dVrh);

    // (6) Output projection: out = O @ Wo^T (64x64 tiles for wave fit)
    gemm_f16_64<<<dim3(D_MODEL / BN5, S / BM5), 128, G5_SMEM>>>(
        dOh, dWoh, out, S, D_MODEL, QDIM, D_MODEL);
}

// round 15
// speedup vs baseline: 1.3814x; 1.1451x over previous
#include <cuda_runtime.h>
#include <cuda_fp16.h>
#include <math.h>
#include <stdint.h>

// Problem constants
#define S 2048
#define D_MODEL 2560
#define NUM_HEADS 32
#define NUM_KV_HEADS 8
#define HEAD_DIM 128
#define QDIM (NUM_HEADS * HEAD_DIM)     // 4096
#define KVDIM (NUM_KV_HEADS * HEAD_DIM) // 1024
#define QKVDIM (QDIM + 2 * KVDIM)       // 6144
#define EPS 1e-6f
#define ROPE_THETA 5000000.0f

// Scratch (no allocs allowed -> __device__ globals)
__device__ __half g_Xh[S * D_MODEL];
__device__ __half g_Wqkvh[QKVDIM * D_MODEL];
__device__ __half g_Woh[D_MODEL * QDIM];
__device__ float  g_QKV[S * QKVDIM];
__device__ __half g_Qh[S * QDIM];
__device__ __half g_Krh[NUM_KV_HEADS * S * HEAD_DIM];
__device__ __half g_Vrh[NUM_KV_HEADS * S * HEAD_DIM];
__device__ __half g_Oh[S * QDIM];

// ----------------------------------------------------------------------------
// helpers
// ----------------------------------------------------------------------------
__device__ __forceinline__ void mma_f16(float* d, const unsigned* a, const unsigned* b) {
    asm volatile(
        "mma.sync.aligned.m16n8k16.row.col.f32.f16.f16.f32 "
        "{%0,%1,%2,%3}, {%4,%5,%6,%7}, {%8,%9}, {%0,%1,%2,%3};"
        : "+f"(d[0]), "+f"(d[1]), "+f"(d[2]), "+f"(d[3])
        : "r"(a[0]), "r"(a[1]), "r"(a[2]), "r"(a[3]), "r"(b[0]), "r"(b[1]));
}

__device__ __forceinline__ void ldsm_x4(unsigned* r, uint32_t addr) {
    asm volatile("ldmatrix.sync.aligned.m8n8.x4.shared.b16 {%0,%1,%2,%3}, [%4];"
                 : "=r"(r[0]), "=r"(r[1]), "=r"(r[2]), "=r"(r[3]) : "r"(addr));
}

__device__ __forceinline__ void ldsm_x4_t(unsigned* r, uint32_t addr) {
    asm volatile("ldmatrix.sync.aligned.m8n8.x4.trans.shared.b16 {%0,%1,%2,%3}, [%4];"
                 : "=r"(r[0]), "=r"(r[1]), "=r"(r[2]), "=r"(r[3]) : "r"(addr));
}

__device__ __forceinline__ void cp_async16(void* smem_dst, const void* gmem_src) {
    unsigned saddr = (unsigned)__cvta_generic_to_shared(smem_dst);
    asm volatile("cp.async.cg.shared.global [%0], [%1], 16;" :: "r"(saddr), "l"(gmem_src));
}
#define CP_COMMIT() asm volatile("cp.async.commit_group;")

__device__ __forceinline__ uint32_t smem_u32(const void* p) {
    uint32_t a;
    asm("{ .reg .u64 t; cvta.to.shared.u64 t, %1; cvt.u32.u64 %0, t; }" : "=r"(a) : "l"(p));
    return a;
}

__device__ __forceinline__ unsigned pack_h2(float a, float b) {
    __half2 h = __floats2half2_rn(a, b);
    return *(unsigned*)&h;
}

// two exponentials (base 2) in one MUFU op
__device__ __forceinline__ unsigned ex2_h2(float a, float b) {
    __half2 h = __floats2half2_rn(a, b);
    unsigned in = *(unsigned*)&h, out;
    asm("ex2.approx.f16x2 %0, %1;" : "=r"(out) : "r"(in));
    return out;
}

// ----------------------------------------------------------------------------
// Fused conversion of all inputs to fp16 (RNE). One launch.
// ----------------------------------------------------------------------------
#define R_N1 (S * D_MODEL / 4)
#define R_N2 (QDIM * D_MODEL / 4)
#define R_N3 (KVDIM * D_MODEL / 4)
#define R_TOT (R_N1 + R_N2 + 2 * R_N3 + R_N2)

__global__ void round_all_kernel(const float* __restrict__ x,
                                 const float* __restrict__ Wq,
                                 const float* __restrict__ Wk,
                                 const float* __restrict__ Wv,
                                 const float* __restrict__ Wo) {
    long i = (long)blockIdx.x * blockDim.x + threadIdx.x;
    if (i >= R_TOT) return;
    const float4* src;
    __half* dst;
    if (i < R_N1) {
        src = (const float4*)x;
        dst = g_Xh;
    } else if (i < R_N1 + R_N2) {
        i -= R_N1;
        src = (const float4*)Wq;
        dst = g_Wqkvh;
    } else if (i < R_N1 + R_N2 + R_N3) {
        i -= R_N1 + R_N2;
        src = (const float4*)Wk;
        dst = g_Wqkvh + (size_t)QDIM * D_MODEL;
    } else if (i < R_N1 + R_N2 + 2 * R_N3) {
        i -= R_N1 + R_N2 + R_N3;
        src = (const float4*)Wv;
        dst = g_Wqkvh + (size_t)(QDIM + KVDIM) * D_MODEL;
    } else {
        i -= R_N1 + R_N2 + 2 * R_N3;
        src = (const float4*)Wo;
        dst = g_Woh;
    }
    float4 v = src[i];
    __half2 h0 = __floats2half2_rn(v.x, v.y);
    __half2 h1 = __floats2half2_rn(v.z, v.w);
    uint2 pk = make_uint2(*(unsigned*)&h0, *(unsigned*)&h1);
    *(uint2*)&dst[i * 4] = pk;
}

// ----------------------------------------------------------------------------
// fp16 NT GEMM 128x64 (QKV projection). Proven kernel, unchanged.
// ----------------------------------------------------------------------------
#define BM4 128
#define BN4 64
#define BK4 64
#define ROWB 144
#define STG4_B ((BM4 + BN4) * ROWB)       // 27648
#define G4_SMEM (2 * STG4_B)              // 55296

__global__ __launch_bounds__(128) void gemm_f16(const __half* __restrict__ A,
                                                const __half* __restrict__ B,
                                                float* __restrict__ C,
                                                int M, int N, int K, int ldc) {
    extern __shared__ char sm4[];
    const uint32_t sbase = smem_u32(sm4);

    const int tid = threadIdx.x;
    const int warp = tid >> 5;
    const int lane = tid & 31;
    const int r = lane >> 2;
    const int cc = lane & 3;
    const int bm0 = blockIdx.y * BM4;
    const int bn0 = blockIdx.x * BN4;
    const int nk = K / BK4;

    const uint32_t lmrow = (lane & 15);
    const uint32_t lmk = (lane >> 4) * 16;

    auto issue = [&](int kt) {
        char* As = sm4 + (kt & 1) * STG4_B;
        char* Bs = As + BM4 * ROWB;
        const int k0 = kt * BK4;
#pragma unroll
        for (int i = 0; i < 8; i++) {
            int task = tid + i * 128;
            int row = task >> 3, ch = task & 7;
            cp_async16(As + row * ROWB + ch * 16,
                       &A[(size_t)(bm0 + row) * K + k0 + ch * 8]);
        }
#pragma unroll
        for (int i = 0; i < 4; i++) {
            int task = tid + i * 128;
            int row = task >> 3, ch = task & 7;
            cp_async16(Bs + row * ROWB + ch * 16,
                       &B[(size_t)(bn0 + row) * K + k0 + ch * 8]);
        }
        CP_COMMIT();
    };

    issue(0);
    if (nk > 1) issue(1);

    float acc[2][8][4];
#pragma unroll
    for (int mt = 0; mt < 2; mt++)
#pragma unroll
        for (int nt = 0; nt < 8; nt++)
#pragma unroll
            for (int i = 0; i < 4; i++) acc[mt][nt][i] = 0.0f;

    for (int kt = 0; kt < nk; kt++) {
        if (kt == nk - 1) asm volatile("cp.async.wait_group 0;" ::: "memory");
        else              asm volatile("cp.async.wait_group 1;" ::: "memory");
        __syncthreads();

        const uint32_t stA = sbase + (kt & 1) * STG4_B;
        const uint32_t stB = stA + BM4 * ROWB;
        const uint32_t aAddr0 = stA + (warp * 32 + lmrow) * ROWB + lmk;
        const uint32_t bAddr0 = stB + lmrow * ROWB + lmk;

#pragma unroll
        for (int ks = 0; ks < 4; ks++) {
            const uint32_t ko = ks * 32;
            unsigned af[2][4];
            ldsm_x4(af[0], aAddr0 + ko);
            ldsm_x4(af[1], aAddr0 + 16 * ROWB + ko);
            unsigned bf[4][4];
#pragma unroll
            for (int p = 0; p < 4; p++)
                ldsm_x4(bf[p], bAddr0 + p * 16 * ROWB + ko);
#pragma unroll
            for (int mt = 0; mt < 2; mt++)
#pragma unroll
                for (int nt = 0; nt < 8; nt++) {
                    unsigned b[2] = { bf[nt >> 1][nt & 1], bf[nt >> 1][2 + (nt & 1)] };
                    mma_f16(acc[mt][nt], af[mt], b);
                }
        }
        __syncthreads();
        if (kt + 2 < nk) issue(kt + 2);
    }

#pragma unroll
    for (int mt = 0; mt < 2; mt++) {
#pragma unroll
        for (int nt = 0; nt < 8; nt++) {
            int row = bm0 + warp * 32 + mt * 16 + r;
            int col = bn0 + nt * 8 + 2 * cc;
            float2 v0 = make_float2(acc[mt][nt][0], acc[mt][nt][1]);
            float2 v1 = make_float2(acc[mt][nt][2], acc[mt][nt][3]);
            *(float2*)&C[(size_t)row * ldc + col] = v0;
            *(float2*)&C[(size_t)(row + 8) * ldc + col] = v1;
        }
    }
}

// ----------------------------------------------------------------------------
// fp16 NT GEMM 64x64 (output projection, wave-fit tiles). Unchanged from R14.
// ----------------------------------------------------------------------------
#define BM5 64
#define BN5 64
#define STG5_B ((BM5 + BN5) * ROWB)       // 18432
#define G5_SMEM (2 * STG5_B)              // 36864

__global__ __launch_bounds__(128) void gemm_f16_64(const __half* __restrict__ A,
                                                   const __half* __restrict__ B,
                                                   float* __restrict__ C,
                                                   int M, int N, int K, int ldc) {
    extern __shared__ char sm5[];
    const uint32_t sbase = smem_u32(sm5);

    const int tid = threadIdx.x;
    const int warp = tid >> 5;
    const int lane = tid & 31;
    const int wm = warp >> 1;
    const int wn = warp & 1;
    const int r = lane >> 2;
    const int cc = lane & 3;
    const int bm0 = blockIdx.y * BM5;
    const int bn0 = blockIdx.x * BN5;
    const int nk = K / BK4;

    const uint32_t lmrow = (lane & 15);
    const uint32_t lmk = (lane >> 4) * 16;

    auto issue = [&](int kt) {
        char* As = sm5 + (kt & 1) * STG5_B;
        char* Bs = As + BM5 * ROWB;
        const int k0 = kt * BK4;
#pragma unroll
        for (int i = 0; i < 4; i++) {
            int task = tid + i * 128;
            int row = task >> 3, ch = task & 7;
            cp_async16(As + row * ROWB + ch * 16,
                       &A[(size_t)(bm0 + row) * K + k0 + ch * 8]);
        }
#pragma unroll
        for (int i = 0; i < 4; i++) {
            int task = tid + i * 128;
            int row = task >> 3, ch = task & 7;
            cp_async16(Bs + row * ROWB + ch * 16,
                       &B[(size_t)(bn0 + row) * K + k0 + ch * 8]);
        }
        CP_COMMIT();
    };

    issue(0);
    if (nk > 1) issue(1);

    float acc[2][4][4];
#pragma unroll
    for (int mt = 0; mt < 2; mt++)
#pragma unroll
        for (int nt = 0; nt < 4; nt++)
#pragma unroll
            for (int i = 0; i < 4; i++) acc[mt][nt][i] = 0.0f;

    for (int kt = 0; kt < nk; kt++) {
        if (kt == nk - 1) asm volatile("cp.async.wait_group 0;" ::: "memory");
        else              asm volatile("cp.async.wait_group 1;" ::: "memory");
        __syncthreads();

        const uint32_t stA = sbase + (kt & 1) * STG5_B;
        const uint32_t stB = stA + BM5 * ROWB;
        const uint32_t aAddr0 = stA + (wm * 32 + lmrow) * ROWB + lmk;
        const uint32_t bAddr0 = stB + (wn * 32 + lmrow) * ROWB + lmk;

#pragma unroll
        for (int ks = 0; ks < 4; ks++) {
            const uint32_t ko = ks * 32;
            unsigned af[2][4];
            ldsm_x4(af[0], aAddr0 + ko);
            ldsm_x4(af[1], aAddr0 + 16 * ROWB + ko);
            unsigned bf[2][4];
            ldsm_x4(bf[0], bAddr0 + ko);
            ldsm_x4(bf[1], bAddr0 + 16 * ROWB + ko);
#pragma unroll
            for (int mt = 0; mt < 2; mt++)
#pragma unroll
                for (int nt = 0; nt < 4; nt++) {
                    unsigned b[2] = { bf[nt >> 1][nt & 1], bf[nt >> 1][2 + (nt & 1)] };
                    mma_f16(acc[mt][nt], af[mt], b);
                }
        }
        __syncthreads();
        if (kt + 2 < nk) issue(kt + 2);
    }

#pragma unroll
    for (int mt = 0; mt < 2; mt++) {
#pragma unroll
        for (int nt = 0; nt < 4; nt++) {
            int row = bm0 + wm * 32 + mt * 16 + r;
            int col = bn0 + wn * 32 + nt * 8 + 2 * cc;
            float2 v0 = make_float2(acc[mt][nt][0], acc[mt][nt][1]);
            float2 v1 = make_float2(acc[mt][nt][2], acc[mt][nt][3]);
            *(float2*)&C[(size_t)row * ldc + col] = v0;
            *(float2*)&C[(size_t)(row + 8) * ldc + col] = v1;
        }
    }
}

// ----------------------------------------------------------------------------
// Merged RMSNorm + RoPE: blockIdx.y 0..31 -> Q head, 32..39 -> KV head (+V copy)
// ----------------------------------------------------------------------------
__global__ void norm_rope_all_kernel(const float* __restrict__ src,
                                     __half* __restrict__ dstQ,
                                     const float* __restrict__ qw,
                                     float* __restrict__ cacheK, __half* __restrict__ Kr,
                                     float* __restrict__ cacheV, __half* __restrict__ Vr,
                                     const float* __restrict__ kw) {
    int s = blockIdx.x;
    int hy = blockIdx.y;
    int d = threadIdx.x;
    bool isQ = hy < NUM_HEADS;
    int h = isQ ? hy : hy - NUM_HEADS;
    int src_off = isQ ? h * HEAD_DIM : QDIM + h * HEAD_DIM;
    const float* w = isQ ? qw : kw;

    __shared__ float sh[HEAD_DIM];
    __shared__ float red[4];

    float x = src[(size_t)s * QKVDIM + src_off + d];

    float sq = x * x;
#pragma unroll
    for (int off = 16; off > 0; off >>= 1)
        sq += __shfl_down_sync(0xffffffff, sq, off);
    if ((d & 31) == 0) red[d >> 5] = sq;
    __syncthreads();
    float var = (red[0] + red[1] + red[2] + red[3]) * (1.0f / HEAD_DIM);
    float r = rsqrtf(var + EPS);
    float xn = x * r * w[d];
    sh[d] = xn;
    __syncthreads();

    int f = d & 63;
    float inv_freq = powf(ROPE_THETA, -((float)f) / 64.0f);
    float ang = (float)s * inv_freq;
    float c = cosf(ang), sn = sinf(ang);
    float out;
    if (d < 64) out = xn * c - sh[d + 64] * sn;
    else        out = xn * c + sh[d - 64] * sn;

    if (isQ) {
        dstQ[(size_t)s * QDIM + h * HEAD_DIM + d] = __float2half_rn(out);
    } else {
        size_t idx = ((size_t)h * S + s) * HEAD_DIM + d;
        cacheK[idx] = out;
        Kr[idx] = __float2half_rn(out);
        float v = src[(size_t)s * QKVDIM + QDIM + KVDIM + h * HEAD_DIM + d];
        cacheV[idx] = v;
        Vr[idx] = __float2half_rn(v);
    }
}

// ----------------------------------------------------------------------------
// Flash attention v4: register P + f16x2 exp + cp.async double-buffered K/V
// stages, V transposed at fragment-load time via ldmatrix.x4.trans.
// smem: Qs 64x272B @0 (17408) | stages: 2 x (K 64x272 + V 64x272) = 69632
// total 87040 B -> 2 CTA/SM.
// ----------------------------------------------------------------------------
#define FQT 64
#define FKT 64
#define F_QS 0
#define F_ST 17408
#define F_STAGE 34816          // K (17408) + V (17408)
#define F_TOT (F_ST + 2 * F_STAGE)   // 87040

__global__ __launch_bounds__(128) void flash_f16(const __half* __restrict__ Kr,
                                                 const __half* __restrict__ Vr) {
    extern __shared__ char fsc[];
    const uint32_t fsb = smem_u32(fsc);
    __half* Qs = (__half*)(fsc + F_QS);

    const int qTile = gridDim.x - 1 - blockIdx.x;   // heavy tiles first
    const int h = blockIdx.y;
    const int g = h >> 2;
    const int tid = threadIdx.x;
    const int warp = tid >> 5;        // 0..3 -> rows warp*16..+16
    const int lane = tid & 31;
    const int r = lane >> 2;
    const int cc = lane & 3;
    const int qBase = qTile * FQT;
    const float scale = 0.08838834764831845f;
    const float sl2e = scale * 1.4426950408889634f;

    const uint32_t lmrow = (lane & 15);
    const uint32_t lmk = (lane >> 4) * 16;

    // load Q tile (64 x 128 halfs), row stride 272B
#pragma unroll
    for (int i = 0; i < 8; i++) {
        int idx = tid + i * 128;
        int row = idx >> 4, ch = idx & 15;
        uint4 v = *(const uint4*)&g_Qh[(size_t)(qBase + row) * QDIM + h * HEAD_DIM + ch * 8];
        *(uint4*)((char*)Qs + row * 272 + ch * 16) = v;
    }

    float oacc[16][4];
#pragma unroll
    for (int nv = 0; nv < 16; nv++)
#pragma unroll
        for (int i = 0; i < 4; i++) oacc[nv][i] = 0.0f;

    float mst0 = -INFINITY, mst1 = -INFINITY, lst0 = 0.0f, lst1 = 0.0f;

    const int nkt = qTile + 1;

    // stage load: K and V tiles (each 64 rows x 16 chunks of 16B)
    auto issue = [&](int kt) {
        char* stK = fsc + F_ST + (kt & 1) * F_STAGE;
        char* stV = stK + 17408;
        const int kBase = kt * FKT;
#pragma unroll
        for (int i = 0; i < 8; i++) {
            int idx = tid + i * 128;
            int row = idx >> 4, ch = idx & 15;
            cp_async16(stK + row * 272 + ch * 16,
                       &Kr[((size_t)g * S + kBase + row) * HEAD_DIM + ch * 8]);
        }
#pragma unroll
        for (int i = 0; i < 8; i++) {
            int idx = tid + i * 128;
            int row = idx >> 4, ch = idx & 15;
            cp_async16(stV + row * 272 + ch * 16,
                       &Vr[((size_t)g * S + kBase + row) * HEAD_DIM + ch * 8]);
        }
        CP_COMMIT();
    };

    issue(0);
    if (nkt > 1) issue(1);

    const uint32_t aQ0 = fsb + F_QS + (warp * 16 + lmrow) * 272 + lmk;
    const int row0g = qBase + warp * 16 + r;
    const int row1g = row0g + 8;

    __syncthreads();   // Q resident (and orders with stage syncs below)

    for (int kt = 0; kt < nkt; kt++) {
        const int kBase = kt * FKT;
        if (kt == nkt - 1) asm volatile("cp.async.wait_group 0;" ::: "memory");
        else               asm volatile("cp.async.wait_group 1;" ::: "memory");
        __syncthreads();

        const uint32_t stK = fsb + F_ST + (kt & 1) * F_STAGE;
        const uint32_t stV = stK + 17408;
        const uint32_t bK0 = stK + lmrow * 272 + lmk;
        const uint32_t bV0 = stV + lmrow * 272 + lmk;   // trans: rows=kv, cols=dims

        // S = Q K^T : warp tile 16 x 64, k=128 -> 8 k16 steps
        float sacc[8][4];
#pragma unroll
        for (int nt = 0; nt < 8; nt++)
#pragma unroll
            for (int i = 0; i < 4; i++) sacc[nt][i] = 0.0f;

#pragma unroll
        for (int ks = 0; ks < 8; ks++) {
            const uint32_t ko = ks * 32;
            unsigned af[4];
            ldsm_x4(af, aQ0 + ko);
            unsigned bf[4][4];
#pragma unroll
            for (int p = 0; p < 4; p++)
                ldsm_x4(bf[p], bK0 + p * 16 * 272 + ko);
#pragma unroll
            for (int nt = 0; nt < 8; nt++) {
                unsigned b[2] = { bf[nt >> 1][nt & 1], bf[nt >> 1][2 + (nt & 1)] };
                mma_f16(sacc[nt], af, b);
            }
        }

        // ---- register softmax (base-2, fp16x2 exp) ----
#pragma unroll
        for (int nt = 0; nt < 8; nt++) {
            int c0 = kBase + nt * 8 + 2 * cc, c1 = c0 + 1;
            if (c0 > row0g) sacc[nt][0] = -1e30f;
            if (c1 > row0g) sacc[nt][1] = -1e30f;
            if (c0 > row1g) sacc[nt][2] = -1e30f;
            if (c1 > row1g) sacc[nt][3] = -1e30f;
        }
        float m0l = -INFINITY, m1l = -INFINITY;
#pragma unroll
        for (int nt = 0; nt < 8; nt++) {
            m0l = fmaxf(m0l, fmaxf(sacc[nt][0], sacc[nt][1]));
            m1l = fmaxf(m1l, fmaxf(sacc[nt][2], sacc[nt][3]));
        }
        m0l = fmaxf(m0l, __shfl_xor_sync(0xffffffffu, m0l, 1));
        m0l = fmaxf(m0l, __shfl_xor_sync(0xffffffffu, m0l, 2));
        m1l = fmaxf(m1l, __shfl_xor_sync(0xffffffffu, m1l, 1));
        m1l = fmaxf(m1l, __shfl_xor_sync(0xffffffffu, m1l, 2));
        float mnew0 = fmaxf(mst0, m0l), mnew1 = fmaxf(mst1, m1l);
        float corr0 = __expf((mst0 - mnew0) * scale);
        float corr1 = __expf((mst1 - mnew1) * scale);

        unsigned ph[8][2];
        float ls0 = 0.0f, ls1 = 0.0f;
#pragma unroll
        for (int nt = 0; nt < 8; nt++) {
            ph[nt][0] = ex2_h2((sacc[nt][0] - mnew0) * sl2e,
                               (sacc[nt][1] - mnew0) * sl2e);
            ph[nt][1] = ex2_h2((sacc[nt][2] - mnew1) * sl2e,
                               (sacc[nt][3] - mnew1) * sl2e);
            float2 p0 = __half22float2(*(__half2*)&ph[nt][0]);
            float2 p1 = __half22float2(*(__half2*)&ph[nt][1]);
            ls0 += p0.x + p0.y;
            ls1 += p1.x + p1.y;
        }
        ls0 += __shfl_xor_sync(0xffffffffu, ls0, 1);
        ls0 += __shfl_xor_sync(0xffffffffu, ls0, 2);
        ls1 += __shfl_xor_sync(0xffffffffu, ls1, 1);
        ls1 += __shfl_xor_sync(0xffffffffu, ls1, 2);
        lst0 = lst0 * corr0 + ls0;
        lst1 = lst1 * corr1 + ls1;
        mst0 = mnew0;
        mst1 = mnew1;

#pragma unroll
        for (int nv = 0; nv < 16; nv++) {
            oacc[nv][0] *= corr0; oacc[nv][1] *= corr0;
            oacc[nv][2] *= corr1; oacc[nv][3] *= corr1;
        }

        // O += P @ V : 4 k16 steps; A (P) from registers, B via ldmatrix.trans.
        // x4.trans at (kv=16ks, dim=16p): r0,r1 = b0,b1 of n-tile dim 16p;
        // r2,r3 = b0,b1 of n-tile 16p+8.
#pragma unroll
        for (int ks = 0; ks < 4; ks++) {
            unsigned af[4] = { ph[2 * ks][0], ph[2 * ks][1],
                               ph[2 * ks + 1][0], ph[2 * ks + 1][1] };
            const uint32_t kvo = ks * 16 * 272;
#pragma unroll
            for (int p = 0; p < 8; p++) {
                unsigned vr[4];
                ldsm_x4_t(vr, bV0 + kvo + p * 32);
                unsigned b0[2] = { vr[0], vr[1] };
                unsigned b1[2] = { vr[2], vr[3] };
                mma_f16(oacc[2 * p], af, b0);
                mma_f16(oacc[2 * p + 1], af, b1);
            }
        }
        __syncthreads();                    // stage kt reads complete
        if (kt + 2 < nkt) issue(kt + 2);    // refill this stage
    }

    // epilogue: normalize, write fp16 O
    float li0 = 1.0f / lst0;
    float li1 = 1.0f / lst1;
#pragma unroll
    for (int nv = 0; nv < 16; nv++) {
        int col = nv * 8 + 2 * cc;
        unsigned v0 = pack_h2(oacc[nv][0] * li0, oacc[nv][1] * li0);
        unsigned v1 = pack_h2(oacc[nv][2] * li1, oacc[nv][3] * li1);
        *(unsigned*)&g_Oh[(size_t)row0g * QDIM + h * HEAD_DIM + col] = v0;
        *(unsigned*)&g_Oh[(size_t)row1g * QDIM + h * HEAD_DIM + col] = v1;
    }
}

// ----------------------------------------------------------------------------
extern "C" void kernel_launch(void* const* d_in, const int* in_sizes, int n_in,
                              void* d_out, int out_size) {
    const float* x  = (const float*)d_in[0];
    const float* Wq = (const float*)d_in[1];
    const float* Wk = (const float*)d_in[2];
    const float* Wv = (const float*)d_in[3];
    const float* Wo = (const float*)d_in[4];
    const float* qw = (const float*)d_in[5];
    const float* kw = (const float*)d_in[6];

    float* out    = (float*)d_out;
    float* cacheK = out + (size_t)S * D_MODEL;
    float* cacheV = cacheK + (size_t)NUM_KV_HEADS * S * HEAD_DIM;

    __half* dXh;   cudaGetSymbolAddress((void**)&dXh, g_Xh);
    __half* dWqkvh;cudaGetSymbolAddress((void**)&dWqkvh, g_Wqkvh);
    __half* dWoh;  cudaGetSymbolAddress((void**)&dWoh, g_Woh);
    float*  dQKV;  cudaGetSymbolAddress((void**)&dQKV, g_QKV);
    __half* dQh;   cudaGetSymbolAddress((void**)&dQh, g_Qh);
    __half* dKrh;  cudaGetSymbolAddress((void**)&dKrh, g_Krh);
    __half* dVrh;  cudaGetSymbolAddress((void**)&dVrh, g_Vrh);
    __half* dOh;   cudaGetSymbolAddress((void**)&dOh, g_Oh);

    cudaFuncSetAttribute(gemm_f16, cudaFuncAttributeMaxDynamicSharedMemorySize, G4_SMEM);
    cudaFuncSetAttribute(gemm_f16_64, cudaFuncAttributeMaxDynamicSharedMemorySize, G5_SMEM);
    cudaFuncSetAttribute(flash_f16, cudaFuncAttributeMaxDynamicSharedMemorySize, F_TOT);

    // (1) convert all inputs to fp16
    round_all_kernel<<<(R_TOT + 255) / 256, 256>>>(x, Wq, Wk, Wv, Wo);

    // (2) fused QKV projection
    gemm_f16<<<dim3(QKVDIM / BN4, S / BM4), 128, G4_SMEM>>>(
        dXh, dWqkvh, dQKV, S, QKVDIM, D_MODEL, QKVDIM);

    // (3) merged norm+rope for Q and KV (+ V copy)
    norm_rope_all_kernel<<<dim3(S, NUM_HEADS + NUM_KV_HEADS), HEAD_DIM>>>(
        dQKV, dQh, qw, cacheK, dKrh, cacheV, dVrh, kw);

    // (4) Flash attention (pipelined K/V stages, trans-ldmatrix V)
    flash_f16<<<dim3(S / FQT, NUM_HEADS), 128, F_TOT>>>(dKrh, dVrh);

    // (5) Output projection (64x64 tiles)
    gemm_f16_64<<<dim3(D_MODEL / BN5, S / BM5), 128, G5_SMEM>>>(
        dOh, dWoh, out, S, D_MODEL, QDIM, D_MODEL);
}